// round 7
// baseline (speedup 1.0000x reference)
#include <cuda_runtime.h>
#include <cstdint>

#define Hh 8
#define Bn 16
#define Ls 1024
#define Dm 512
#define M_ALL (Bn*Ls)              /* 16384 */
#define OUT_ELEMS (Bn*Ls*Dm)       /* 8388608 */
#define NROWS (Hh*Bn*Ls)           /* 131072 */
#define CC   0.0637588536f         /* (1/sqrt(512)) * log2(e) */

// ---------------- static device scratch ----------------
__device__ float g_qs[M_ALL*Dm];        // [m][h*64+e]
__device__ float g_ks[M_ALL*Dm];
__device__ float g_vs[M_ALL*Dm];
__device__ float g_headout[M_ALL*Dm];   // [m][h*64+e]
__device__ float g_projout[M_ALL*Dm];
__device__ float g_p[NROWS];
__device__ int   g_amax[NROWS];

// ---------------- helpers ----------------
__device__ __forceinline__ uint32_t smem_u32(const void* p) {
    uint32_t a;
    asm("{ .reg .u64 t; cvta.to.shared.u64 t, %1; cvt.u32.u64 %0, t; }" : "=r"(a) : "l"(p));
    return a;
}
__device__ __forceinline__ void cp_async16(void* sdst, const void* gsrc) {
    uint32_t s = smem_u32(sdst);
    asm volatile("cp.async.ca.shared.global [%0], [%1], 16;" :: "r"(s), "l"(gsrc));
}
#define CP_COMMIT() asm volatile("cp.async.commit_group;" ::: "memory")
#define CP_WAIT1()  asm volatile("cp.async.wait_group 1;" ::: "memory")
#define CP_WAIT0()  asm volatile("cp.async.wait_group 0;" ::: "memory")

// fp32 -> tf32 hi (rounded) + raw fp32 residual (exact; HMMA truncates)
__device__ __forceinline__ void splitf(float x, uint32_t& hi, uint32_t& lo) {
    uint32_t h;
    asm("cvt.rna.tf32.f32 %0, %1;" : "=r"(h) : "f"(x));
    hi = h;
    lo = __float_as_uint(x - __uint_as_float(h));
}
__device__ __forceinline__ void mma8(float* d, const uint32_t* a, const uint32_t* b) {
    asm volatile("mma.sync.aligned.m16n8k8.row.col.f32.tf32.tf32.f32 "
                 "{%0,%1,%2,%3}, {%4,%5,%6,%7}, {%8,%9}, {%0,%1,%2,%3};"
                 : "+f"(d[0]), "+f"(d[1]), "+f"(d[2]), "+f"(d[3])
                 : "r"(a[0]), "r"(a[1]), "r"(a[2]), "r"(a[3]),
                   "r"(b[0]), "r"(b[1]));
}
// bf16 pair split: two consecutive-k fp32 -> packed bf16x2 hi + bf16x2 lo
__device__ __forceinline__ void split2(float x0, float x1, uint32_t& hi, uint32_t& lo) {
    uint32_t h;
    asm("cvt.rn.bf16x2.f32 %0, %1, %2;" : "=r"(h) : "f"(x1), "f"(x0));
    float h0 = __uint_as_float(h << 16);
    float h1 = __uint_as_float(h & 0xffff0000u);
    float r0 = x0 - h0, r1 = x1 - h1;
    asm("cvt.rn.bf16x2.f32 %0, %1, %2;" : "=r"(lo) : "f"(r1), "f"(r0));
    hi = h;
}
__device__ __forceinline__ void mma16(float* d, const uint32_t* a, const uint32_t* b) {
    asm volatile("mma.sync.aligned.m16n8k16.row.col.f32.bf16.bf16.f32 "
                 "{%0,%1,%2,%3}, {%4,%5,%6,%7}, {%8,%9}, {%0,%1,%2,%3};"
                 : "+f"(d[0]), "+f"(d[1]), "+f"(d[2]), "+f"(d[3])
                 : "r"(a[0]), "r"(a[1]), "r"(a[2]), "r"(a[3]),
                   "r"(b[0]), "r"(b[1]));
}
// 2^z, |z| modest: 5-term poly + exponent add (~2e-6 rel err)
__device__ __forceinline__ float fexp2s(float z) {
    int   e  = __float2int_rn(z);
    float f  = z - (float)e;
    float p = 1.3333558146428443e-3f;
    p = fmaf(p, f, 9.6181291976233960e-3f);
    p = fmaf(p, f, 5.5504108664821580e-2f);
    p = fmaf(p, f, 2.4022650695910071e-1f);
    p = fmaf(p, f, 6.9314718055994531e-1f);
    p = fmaf(p, f, 1.0f);
    return __int_as_float(__float_as_int(p) + (e << 23));
}

// ============================================================================
// GEMM scaffolding: 128(M) x 32(N) CTA tile, 128 thr = 4 warps along M,
// warp tile 32x32; K chunks of 32, cp.async double buffer; 4 CTAs/SM.
// smem: A[2][128][36] + B[2][32][36] = 46080 B
// ============================================================================
#define GPAD 36
#define G_SMEM ((2*128*GPAD + 2*32*GPAD)*4)   /* 46080 */

#define A_LOAD(buf, k0_) do {                                                    \
        int k0 = (k0_);                                                          \
        const float* Asrc; int lda, kc;                                          \
        if (k0 < K1) { Asrc = A1; lda = K1;     kc = k0; }                       \
        else         { Asrc = A2; lda = K - K1; kc = k0 - K1; }                  \
        _Pragma("unroll")                                                        \
        for (int i = 0; i < 8; i++) {                                            \
            int id = tid + i * 128;                                              \
            int row = id >> 3, c4 = (id & 7) * 4;                                \
            cp_async16(Abuf[buf] + row*GPAD + c4,                                \
                       Asrc + (size_t)(m0 + row)*lda + kc + c4);                 \
        }                                                                         \
    } while (0)

#define G_EPILOGUE()                                                             \
    _Pragma("unroll")                                                            \
    for (int mt = 0; mt < 2; mt++) {                                             \
        _Pragma("unroll")                                                        \
        for (int nt = 0; nt < 4; nt++) {                                         \
            int row = m0 + wid*32 + mt*16 + lr;                                  \
            int col = n0 + nt*8 + 2*lc;                                          \
            float bx = 0.f, by = 0.f;                                            \
            if (bias) { bx = bias[col]; by = bias[col + 1]; }                    \
            *(float2*)(C + (size_t)row * Dm + col) =                             \
                make_float2(acc[mt][nt][0] + bx, acc[mt][nt][1] + by);           \
            *(float2*)(C + (size_t)(row + 8) * Dm + col) =                       \
                make_float2(acc[mt][nt][2] + bx, acc[mt][nt][3] + by);           \
        }                                                                        \
    }

#define ACC_INIT() float acc[2][4][4];                                           \
    _Pragma("unroll") for (int a_ = 0; a_ < 2; a_++)                             \
    _Pragma("unroll") for (int b_ = 0; b_ < 4; b_++)                             \
    _Pragma("unroll") for (int c_ = 0; c_ < 4; c_++) acc[a_][b_][c_] = 0.f;

// ---- tf32 3-product core, B streamed from W[h][d][e] ([k][n] layout) ----
// Wh must already point at the 32-col slice (stride 64). Q/K projections.
__device__ __forceinline__ void gemm_core_tf32_bt(
    const float* __restrict__ A1, const float* __restrict__ Wh,
    float* __restrict__ C, int m0, int n0, float* sm)
{
    const float* A2 = A1; const int K1 = Dm, K = Dm;
    const float* bias = nullptr;
    float* Abuf[2] = { sm,              sm + 128*GPAD };
    float* Bbuf[2] = { sm + 2*128*GPAD, sm + 2*128*GPAD + 32*GPAD };
    const int tid = threadIdx.x;
    const int wid = tid >> 5, lane = tid & 31;
    const int lr = lane >> 2, lc = lane & 3;
    const int NC = K / 32;

#define B_LOAD_BT(buf, k0_) do {                                                 \
        int k0 = (k0_);                                                          \
        _Pragma("unroll")                                                        \
        for (int i = 0; i < 2; i++) {                                            \
            int id = tid + i * 128;                                              \
            int kk = id >> 3, n4 = (id & 7) * 4;                                 \
            cp_async16(Bbuf[buf] + kk*GPAD + n4, Wh + (size_t)(k0 + kk)*64 + n4);\
        }                                                                         \
    } while (0)

    A_LOAD(0, 0); B_LOAD_BT(0, 0); CP_COMMIT();
    A_LOAD(1, 32); B_LOAD_BT(1, 32); CP_COMMIT();
    ACC_INIT()

    for (int c = 0; c < NC; c++) {
        if (c < NC - 1) CP_WAIT1(); else CP_WAIT0();
        __syncthreads();
        const int buf = c & 1;
        const float* Ab = Abuf[buf] + wid * 32 * GPAD;
        const float* Bb = Bbuf[buf];
#pragma unroll
        for (int ks = 0; ks < 4; ks++) {
            const int kb = ks * 8 + lc;
            uint32_t bh[4][2], bl[4][2];
#pragma unroll
            for (int nt = 0; nt < 4; nt++) {
                int nl = nt*8 + lr;
                splitf(Bb[kb*GPAD + nl],     bh[nt][0], bl[nt][0]);
                splitf(Bb[(kb+4)*GPAD + nl], bh[nt][1], bl[nt][1]);
            }
#pragma unroll
            for (int mt = 0; mt < 2; mt++) {
                uint32_t ah[4], al[4];
                splitf(Ab[(mt*16 + lr    )*GPAD + kb],     ah[0], al[0]);
                splitf(Ab[(mt*16 + lr + 8)*GPAD + kb],     ah[1], al[1]);
                splitf(Ab[(mt*16 + lr    )*GPAD + kb + 4], ah[2], al[2]);
                splitf(Ab[(mt*16 + lr + 8)*GPAD + kb + 4], ah[3], al[3]);
#pragma unroll
                for (int nt = 0; nt < 4; nt++) {
                    mma8(acc[mt][nt], ah, bh[nt]);
                    mma8(acc[mt][nt], ah, bl[nt]);
                    mma8(acc[mt][nt], al, bh[nt]);
                }
            }
        }
        __syncthreads();
        if (c + 2 < NC) { A_LOAD(buf, (c + 2) * 32); B_LOAD_BT(buf, (c + 2) * 32); CP_COMMIT(); }
    }
    G_EPILOGUE()
#undef B_LOAD_BT
}

// ---- bf16 split 3-product core, B from W[h][d][e] ([k][n] layout): V proj ----
__device__ __forceinline__ void gemm_core_bf_bt(
    const float* __restrict__ A1, const float* __restrict__ Wh,
    float* __restrict__ C, int m0, int n0, float* sm)
{
    const float* A2 = A1; const int K1 = Dm, K = Dm;
    const float* bias = nullptr;
    float* Abuf[2] = { sm,              sm + 128*GPAD };
    float* Bbuf[2] = { sm + 2*128*GPAD, sm + 2*128*GPAD + 32*GPAD };
    const int tid = threadIdx.x;
    const int wid = tid >> 5, lane = tid & 31;
    const int lr = lane >> 2, lc = lane & 3;
    const int NC = K / 32;

#define B_LOAD_BT(buf, k0_) do {                                                 \
        int k0 = (k0_);                                                          \
        _Pragma("unroll")                                                        \
        for (int i = 0; i < 2; i++) {                                            \
            int id = tid + i * 128;                                              \
            int kk = id >> 3, n4 = (id & 7) * 4;                                 \
            cp_async16(Bbuf[buf] + kk*GPAD + n4, Wh + (size_t)(k0 + kk)*64 + n4);\
        }                                                                         \
    } while (0)

    A_LOAD(0, 0); B_LOAD_BT(0, 0); CP_COMMIT();
    A_LOAD(1, 32); B_LOAD_BT(1, 32); CP_COMMIT();
    ACC_INIT()

    for (int c = 0; c < NC; c++) {
        if (c < NC - 1) CP_WAIT1(); else CP_WAIT0();
        __syncthreads();
        const int buf = c & 1;
        const float* Ab = Abuf[buf] + wid * 32 * GPAD;
        const float* Bb = Bbuf[buf];
#pragma unroll
        for (int ks = 0; ks < 2; ks++) {
            const int kb = ks * 16 + 2 * lc;
            uint32_t bh[4][2], bl[4][2];
#pragma unroll
            for (int nt = 0; nt < 4; nt++) {
                int nl = nt*8 + lr;
                split2(Bb[kb*GPAD + nl],     Bb[(kb+1)*GPAD + nl], bh[nt][0], bl[nt][0]);
                split2(Bb[(kb+8)*GPAD + nl], Bb[(kb+9)*GPAD + nl], bh[nt][1], bl[nt][1]);
            }
#pragma unroll
            for (int mt = 0; mt < 2; mt++) {
                uint32_t ah[4], al[4];
                float2 a00 = *(const float2*)(Ab + (mt*16 + lr    )*GPAD + kb);
                float2 a10 = *(const float2*)(Ab + (mt*16 + lr + 8)*GPAD + kb);
                float2 a01 = *(const float2*)(Ab + (mt*16 + lr    )*GPAD + kb + 8);
                float2 a11 = *(const float2*)(Ab + (mt*16 + lr + 8)*GPAD + kb + 8);
                split2(a00.x, a00.y, ah[0], al[0]);
                split2(a10.x, a10.y, ah[1], al[1]);
                split2(a01.x, a01.y, ah[2], al[2]);
                split2(a11.x, a11.y, ah[3], al[3]);
#pragma unroll
                for (int nt = 0; nt < 4; nt++) {
                    mma16(acc[mt][nt], ah, bh[nt]);
                    mma16(acc[mt][nt], ah, bl[nt]);
                    mma16(acc[mt][nt], al, bh[nt]);
                }
            }
        }
        __syncthreads();
        if (c + 2 < NC) { A_LOAD(buf, (c + 2) * 32); B_LOAD_BT(buf, (c + 2) * 32); CP_COMMIT(); }
    }
    G_EPILOGUE()
#undef B_LOAD_BT
}

// ---- bf16 split 3-product core, B = [n][k] row-major weights (proj/lin) ----
__device__ __forceinline__ void gemm_core_bf(
    const float* __restrict__ A1, const float* __restrict__ A2, int K1, int K,
    const float* __restrict__ Bm, const float* __restrict__ bias,
    float* __restrict__ C, int m0, int n0, float* sm)
{
    float* Abuf[2] = { sm,              sm + 128*GPAD };
    float* Bbuf[2] = { sm + 2*128*GPAD, sm + 2*128*GPAD + 32*GPAD };
    const int tid = threadIdx.x;
    const int wid = tid >> 5, lane = tid & 31;
    const int lr = lane >> 2, lc = lane & 3;
    const int NC = K / 32;

#define B_LOAD_NK(buf, k0_) do {                                                 \
        int k0 = (k0_);                                                          \
        _Pragma("unroll")                                                        \
        for (int i = 0; i < 2; i++) {                                            \
            int id = tid + i * 128;                                              \
            int row = id >> 3, c4 = (id & 7) * 4;                                \
            cp_async16(Bbuf[buf] + row*GPAD + c4,                                \
                       Bm + (size_t)(n0 + row)*K + k0 + c4);                     \
        }                                                                         \
    } while (0)

    A_LOAD(0, 0); B_LOAD_NK(0, 0); CP_COMMIT();
    A_LOAD(1, 32); B_LOAD_NK(1, 32); CP_COMMIT();
    ACC_INIT()

    for (int c = 0; c < NC; c++) {
        if (c < NC - 1) CP_WAIT1(); else CP_WAIT0();
        __syncthreads();
        const int buf = c & 1;
        const float* Ab = Abuf[buf] + wid * 32 * GPAD;
        const float* Bb = Bbuf[buf];
#pragma unroll
        for (int ks = 0; ks < 2; ks++) {
            const int kb = ks * 16 + 2 * lc;
            uint32_t bh[4][2], bl[4][2];
#pragma unroll
            for (int nt = 0; nt < 4; nt++) {
                float2 b0 = *(const float2*)(Bb + (nt*8 + lr)*GPAD + kb);
                float2 b1 = *(const float2*)(Bb + (nt*8 + lr)*GPAD + kb + 8);
                split2(b0.x, b0.y, bh[nt][0], bl[nt][0]);
                split2(b1.x, b1.y, bh[nt][1], bl[nt][1]);
            }
#pragma unroll
            for (int mt = 0; mt < 2; mt++) {
                uint32_t ah[4], al[4];
                float2 a00 = *(const float2*)(Ab + (mt*16 + lr    )*GPAD + kb);
                float2 a10 = *(const float2*)(Ab + (mt*16 + lr + 8)*GPAD + kb);
                float2 a01 = *(const float2*)(Ab + (mt*16 + lr    )*GPAD + kb + 8);
                float2 a11 = *(const float2*)(Ab + (mt*16 + lr + 8)*GPAD + kb + 8);
                split2(a00.x, a00.y, ah[0], al[0]);
                split2(a10.x, a10.y, ah[1], al[1]);
                split2(a01.x, a01.y, ah[2], al[2]);
                split2(a11.x, a11.y, ah[3], al[3]);
#pragma unroll
                for (int nt = 0; nt < 4; nt++) {
                    mma16(acc[mt][nt], ah, bh[nt]);
                    mma16(acc[mt][nt], ah, bl[nt]);
                    mma16(acc[mt][nt], al, bh[nt]);
                }
            }
        }
        __syncthreads();
        if (c + 2 < NC) { A_LOAD(buf, (c + 2) * 32); B_LOAD_NK(buf, (c + 2) * 32); CP_COMMIT(); }
    }
    G_EPILOGUE()
#undef B_LOAD_NK
}

// Q/K projections: z={q,k}; blockIdx.x = 16 n-tiles (head = x>>1)
__global__ __launch_bounds__(128, 4) void qk_mma_bt(
    const float* __restrict__ qd, const float* __restrict__ kd,
    const float* __restrict__ wq, const float* __restrict__ wk)
{
    extern __shared__ float sm[];
    const int z = blockIdx.z;
    const int head = blockIdx.x >> 1;
    const float* A = (z == 0) ? qd : kd;
    const float* W = ((z == 0) ? wq : wk) + (size_t)head * Dm * 64 + (blockIdx.x & 1) * 32;
    float* C = (z == 0) ? g_qs : g_ks;
    gemm_core_tf32_bt(A, W, C, blockIdx.y * 128, blockIdx.x * 32, sm);
}

__global__ __launch_bounds__(128, 4) void v_mma_bt(
    const float* __restrict__ vd, const float* __restrict__ wv)
{
    extern __shared__ float sm[];
    const int head = blockIdx.x >> 1;
    const float* W = wv + (size_t)head * Dm * 64 + (blockIdx.x & 1) * 32;
    gemm_core_bf_bt(vd, W, g_vs, blockIdx.y * 128, blockIdx.x * 32, sm);
}

__global__ __launch_bounds__(128, 4) void gemm_bf_mma(
    const float* __restrict__ A1, const float* __restrict__ A2, int K1, int K,
    const float* __restrict__ Bm, const float* __restrict__ bias, float* __restrict__ C)
{
    extern __shared__ float sm[];
    gemm_core_bf(A1, A2, K1, K, Bm, bias, C, blockIdx.y * 128, blockIdx.x * 32, sm);
}

// ============================================================================
// QK^T + softmax stats + dense attn fill, fused. CTA = (h, b, 128 q rows);
// 32 K-tiles of 32 rows; warp tile 32(q)x32(s), each warp sees ALL s-cols of
// its rows -> quad-shuffle-only reduction. 4 CTAs/SM.
// smem: Q[128][68] + K[2][32][68] = 52224
// ============================================================================
#define APAD 68
#define S_SMEM ((128*APAD + 2*32*APAD)*4)  /* 52224 */
__global__ __launch_bounds__(128, 4) void attn_stats_mma(float* __restrict__ attn)
{
    extern __shared__ float sm[];
    float* Qs = sm;
    float* Kbuf[2] = { sm + 128*APAD, sm + 128*APAD + 32*APAD };

    const int tid = threadIdx.x;
    const int h = blockIdx.z, b = blockIdx.y, q0 = blockIdx.x * 128;
    const int wid = tid >> 5, lane = tid & 31;
    const int lr = lane >> 2, lc = lane & 3;

    const float* Qg = g_qs + ((size_t)(b * Ls + q0)) * Dm + h * 64;
    const float* Kg = g_ks + ((size_t)(b * Ls)) * Dm + h * 64;
    const size_t rowbase = (size_t)(h * Bn + b) * Ls + q0;

#pragma unroll
    for (int i = 0; i < 16; i++) {
        int id = tid + i * 128;
        int row = id >> 4, c4 = (id & 15) * 4;
        cp_async16(Qs + row*APAD + c4, Qg + (size_t)row * Dm + c4);
    }
    CP_COMMIT();

#define K_LOAD(buf, t_) do {                                                    \
        _Pragma("unroll")                                                       \
        for (int i = 0; i < 4; i++) {                                           \
            int id = tid + i * 128;                                             \
            int row = id >> 4, c4 = (id & 15) * 4;                              \
            cp_async16(Kbuf[buf] + row*APAD + c4,                               \
                       Kg + (size_t)((t_)*32 + row) * Dm + c4);                 \
        }                                                                       \
    } while (0)

    K_LOAD(0, 0); CP_COMMIT();
    K_LOAD(1, 1); CP_COMMIT();

    float rm[4], rs[4];
    int ridx[4];
#pragma unroll
    for (int i = 0; i < 4; i++) { rm[i] = -1e30f; rs[i] = 0.f; ridx[i] = 0; }

    for (int t = 0; t < 32; t++) {
        if (t < 31) CP_WAIT1(); else CP_WAIT0();
        __syncthreads();
        const int buf = t & 1;
        const float* Ab = Qs + wid * 32 * APAD;
        const float* Bb = Kbuf[buf];

        ACC_INIT()

#pragma unroll
        for (int ks = 0; ks < 8; ks++) {
            const int kb = ks * 8 + lc;
            uint32_t bh[4][2], bl[4][2];
#pragma unroll
            for (int nt = 0; nt < 4; nt++) {
                int nl = nt*8 + lr;
                splitf(Bb[nl*APAD + kb],     bh[nt][0], bl[nt][0]);
                splitf(Bb[nl*APAD + kb + 4], bh[nt][1], bl[nt][1]);
            }
#pragma unroll
            for (int mt = 0; mt < 2; mt++) {
                uint32_t ah[4], al[4];
                splitf(Ab[(mt*16 + lr    )*APAD + kb],     ah[0], al[0]);
                splitf(Ab[(mt*16 + lr + 8)*APAD + kb],     ah[1], al[1]);
                splitf(Ab[(mt*16 + lr    )*APAD + kb + 4], ah[2], al[2]);
                splitf(Ab[(mt*16 + lr + 8)*APAD + kb + 4], ah[3], al[3]);
#pragma unroll
                for (int nt = 0; nt < 4; nt++) {
                    mma8(acc[mt][nt], ah, bh[nt]);
                    mma8(acc[mt][nt], ah, bl[nt]);
                    mma8(acc[mt][nt], al, bh[nt]);
                }
            }
        }

        // streaming zero-fill of this CTA's attn slice, s-range [t*32, t*32+32)
        {
            float4 z4 = make_float4(0.f, 0.f, 0.f, 0.f);
#pragma unroll
            for (int i = 0; i < 8; i++) {
                int id = tid + i * 128;
                int r = id >> 3, f4 = id & 7;
                __stcs((float4*)(attn + (rowbase + r) * Ls + t * 32 + f4 * 4), z4);
            }
        }

        // fold tile into per-thread stats (raw sum + explicit max/argmax)
        const int sbase = t * 32 + 2 * lc;
#pragma unroll
        for (int mt = 0; mt < 2; mt++) {
#pragma unroll
            for (int half = 0; half < 2; half++) {
                const int r4 = mt * 2 + half;
                float m = rm[r4], s_ = rs[r4];
                int id_ = ridx[r4];
#pragma unroll
                for (int nt = 0; nt < 4; nt++) {
#pragma unroll
                    for (int j = 0; j < 2; j++) {
                        float v = acc[mt][nt][half*2 + j];
                        if (v > m) { m = v; id_ = sbase + nt*8 + j; }
                        s_ += fexp2s(v * CC);
                    }
                }
                rm[r4] = m; rs[r4] = s_; ridx[r4] = id_;
            }
        }
        __syncthreads();
        if (t + 2 < 32) { K_LOAD(buf, t + 2); CP_COMMIT(); }
    }

    // quad reduce over lc; lane lc==0 holds the full row result
#pragma unroll
    for (int r4 = 0; r4 < 4; r4++) {
        float m = rm[r4], s_ = rs[r4];
        int id_ = ridx[r4];
#pragma unroll
        for (int off = 1; off <= 2; off <<= 1) {
            float om = __shfl_xor_sync(0xffffffffu, m, off);
            float os = __shfl_xor_sync(0xffffffffu, s_, off);
            int   oi = __shfl_xor_sync(0xffffffffu, id_, off);
            s_ += os;
            if (om > m) { m = om; id_ = oi; }
        }
        rm[r4] = m; rs[r4] = s_; ridx[r4] = id_;
    }
    __syncthreads();   // order all zero-fill stores before the scatter below

    if (lc == 0) {
#pragma unroll
        for (int r4 = 0; r4 < 4; r4++) {
            int rowl = wid*32 + (r4 >> 1)*16 + (r4 & 1)*8 + lr;
            float p = fexp2s(rm[r4] * CC) / rs[r4];
            int row = (int)rowbase + rowl;
            g_p[row] = p;
            g_amax[row] = ridx[r4];
            attn[(rowbase + rowl) * Ls + ridx[r4]] = p;
        }
    }
#undef K_LOAD
}

// ============================================================================
// attn @ V collapsed to a vectorized gather
// ============================================================================
__global__ void gather_kernel()
{
    int idx4 = blockIdx.x * blockDim.x + threadIdx.x;   // over M_ALL*Dm/4
    if (idx4 >= M_ALL * Dm / 4) return;
    int e4 = idx4 & 15;            // 16 float4 per head
    int h  = (idx4 >> 4) & 7;
    int m  = idx4 >> 7;            // b*L + q
    int b  = m >> 10;
    int q  = m & 1023;
    int row = (h * Bn + b) * Ls + q;
    float p = g_p[row];
    int   s = g_amax[row];
    float4 v = *(const float4*)(g_vs + ((size_t)(b * Ls + s)) * Dm + h * 64 + e4 * 4);
    v.x *= p; v.y *= p; v.z *= p; v.w *= p;
    *(float4*)(g_headout + (size_t)idx4 * 4) = v;
}

// ============================================================================
extern "C" void kernel_launch(void* const* d_in, const int* in_sizes, int n_in,
                              void* d_out, int out_size)
{
    const float* q_data = (const float*)d_in[0];
    const float* k_data = (const float*)d_in[1];
    const float* v_data = (const float*)d_in[2];
    const float* w_qs   = (const float*)d_in[3];
    const float* w_ks   = (const float*)d_in[4];
    const float* w_vs   = (const float*)d_in[5];
    const float* proj_w = (const float*)d_in[6];
    const float* proj_b = (const float*)d_in[7];
    const float* lin_w  = (const float*)d_in[8];
    const float* lin_b  = (const float*)d_in[9];

    float* out  = (float*)d_out;                    // [B, L, D]
    float* attn = out + OUT_ELEMS;                  // [H*B, L, L]

    float *p_ho, *p_po;
    cudaGetSymbolAddress((void**)&p_ho, g_headout);
    cudaGetSymbolAddress((void**)&p_po, g_projout);

    cudaFuncSetAttribute(qk_mma_bt,  cudaFuncAttributeMaxDynamicSharedMemorySize, G_SMEM);
    cudaFuncSetAttribute(v_mma_bt,   cudaFuncAttributeMaxDynamicSharedMemorySize, G_SMEM);
    cudaFuncSetAttribute(gemm_bf_mma, cudaFuncAttributeMaxDynamicSharedMemorySize, G_SMEM);
    cudaFuncSetAttribute(attn_stats_mma, cudaFuncAttributeMaxDynamicSharedMemorySize, S_SMEM);

    // 1) Q/K projections (tf32 3-product, weights read in-place)
    qk_mma_bt<<<dim3(16, 128, 2), 128, G_SMEM>>>(q_data, k_data, w_qs, w_ks);

    // 1b) V projection (bf16 split 3-product)
    v_mma_bt<<<dim3(16, 128), 128, G_SMEM>>>(v_data, w_vs);

    // 2) QK^T + softmax stats + full dense attn-output fill (fused)
    attn_stats_mma<<<dim3(8, 16, 8), 128, S_SMEM>>>(attn);

    // 3) attn @ V collapsed to gather (vectorized)
    gather_kernel<<<(M_ALL * Dm / 4 + 255) / 256, 256>>>();

    // 4) output projection (bf16)
    gemm_bf_mma<<<dim3(16, 128), 128, G_SMEM>>>(p_ho, p_ho, Dm, Dm, proj_w, proj_b, p_po);

    // 5) final linear (bf16): out = [q_data | projout] @ lin_w^T + lin_b
    gemm_bf_mma<<<dim3(16, 128), 128, G_SMEM>>>(q_data, p_po, Dm, 2*Dm, lin_w, lin_b, out);
}

// round 8
// speedup vs baseline: 1.1367x; 1.1367x over previous
#include <cuda_runtime.h>
#include <cstdint>

#define Hh 8
#define Bn 16
#define Ls 1024
#define Dm 512
#define M_ALL (Bn*Ls)              /* 16384 */
#define OUT_ELEMS (Bn*Ls*Dm)       /* 8388608 */
#define NROWS (Hh*Bn*Ls)           /* 131072 */
#define CC   0.0637588536f         /* (1/sqrt(512)) * log2(e) */

// ---------------- static device scratch ----------------
__device__ float g_qs[M_ALL*Dm];        // [m][h*64+e]
__device__ float g_ks[M_ALL*Dm];
__device__ float g_vs[M_ALL*Dm];
__device__ float g_headout[M_ALL*Dm];   // [m][h*64+e]
__device__ float g_projout[M_ALL*Dm];
__device__ float g_p[NROWS];
__device__ int   g_amax[NROWS];

// ---------------- helpers ----------------
__device__ __forceinline__ uint32_t smem_u32(const void* p) {
    uint32_t a;
    asm("{ .reg .u64 t; cvta.to.shared.u64 t, %1; cvt.u32.u64 %0, t; }" : "=r"(a) : "l"(p));
    return a;
}
__device__ __forceinline__ void cp_async16(void* sdst, const void* gsrc) {
    uint32_t s = smem_u32(sdst);
    asm volatile("cp.async.ca.shared.global [%0], [%1], 16;" :: "r"(s), "l"(gsrc));
}
#define CP_COMMIT() asm volatile("cp.async.commit_group;" ::: "memory")
#define CP_WAIT1()  asm volatile("cp.async.wait_group 1;" ::: "memory")
#define CP_WAIT0()  asm volatile("cp.async.wait_group 0;" ::: "memory")

// fp32 -> tf32 hi (rounded) + raw fp32 residual (exact; HMMA truncates)
__device__ __forceinline__ void splitf(float x, uint32_t& hi, uint32_t& lo) {
    uint32_t h;
    asm("cvt.rna.tf32.f32 %0, %1;" : "=r"(h) : "f"(x));
    hi = h;
    lo = __float_as_uint(x - __uint_as_float(h));
}
__device__ __forceinline__ void mma8(float* d, const uint32_t* a, const uint32_t* b) {
    asm volatile("mma.sync.aligned.m16n8k8.row.col.f32.tf32.tf32.f32 "
                 "{%0,%1,%2,%3}, {%4,%5,%6,%7}, {%8,%9}, {%0,%1,%2,%3};"
                 : "+f"(d[0]), "+f"(d[1]), "+f"(d[2]), "+f"(d[3])
                 : "r"(a[0]), "r"(a[1]), "r"(a[2]), "r"(a[3]),
                   "r"(b[0]), "r"(b[1]));
}
// bf16 pair split: two consecutive-k fp32 -> packed bf16x2 hi + bf16x2 lo
__device__ __forceinline__ void split2(float x0, float x1, uint32_t& hi, uint32_t& lo) {
    uint32_t h;
    asm("cvt.rn.bf16x2.f32 %0, %1, %2;" : "=r"(h) : "f"(x1), "f"(x0));
    float h0 = __uint_as_float(h << 16);
    float h1 = __uint_as_float(h & 0xffff0000u);
    float r0 = x0 - h0, r1 = x1 - h1;
    asm("cvt.rn.bf16x2.f32 %0, %1, %2;" : "=r"(lo) : "f"(r1), "f"(r0));
    hi = h;
}
__device__ __forceinline__ void mma16(float* d, const uint32_t* a, const uint32_t* b) {
    asm volatile("mma.sync.aligned.m16n8k16.row.col.f32.bf16.bf16.f32 "
                 "{%0,%1,%2,%3}, {%4,%5,%6,%7}, {%8,%9}, {%0,%1,%2,%3};"
                 : "+f"(d[0]), "+f"(d[1]), "+f"(d[2]), "+f"(d[3])
                 : "r"(a[0]), "r"(a[1]), "r"(a[2]), "r"(a[3]),
                   "r"(b[0]), "r"(b[1]));
}
// hardware exp2 (MUFU pipe: 1 issue slot; offloads the FMA/ALU pipes)
__device__ __forceinline__ float fex2(float z) {
    float r;
    asm("ex2.approx.f32 %0, %1;" : "=f"(r) : "f"(z));
    return r;
}

// ============================================================================
// GEMM scaffolding: 128(M) x 64(N) CTA tile, 128 thr = 4 warps 2(M)x2(N),
// warp tile 64x32, K chunks of 32, cp.async double buffer, 3 CTAs/SM.
// ============================================================================
#define GPAD 36
#define BTPAD 68
#define G_SMEM ((2*128*GPAD + 2*64*GPAD)*4)       /* 55296: [n][k]-weights form */
#define G_SMEM_BT ((2*128*GPAD + 2*32*BTPAD)*4)   /* 54272: [k][n]-weights form */

// A loader (activations, [m][k] gmem, possibly concatenated)
#define A_LOAD(buf, k0_) do {                                                    \
        int k0 = (k0_);                                                          \
        const float* Asrc; int lda, kc;                                          \
        if (k0 < K1) { Asrc = A1; lda = K1;     kc = k0; }                       \
        else         { Asrc = A2; lda = K - K1; kc = k0 - K1; }                  \
        _Pragma("unroll")                                                        \
        for (int i = 0; i < 8; i++) {                                            \
            int id = tid + i * 128;                                              \
            int row = id >> 3, c4 = (id & 7) * 4;                                \
            cp_async16(Abuf[buf] + row*GPAD + c4,                                \
                       Asrc + (size_t)(m0 + row)*lda + kc + c4);                 \
        }                                                                         \
    } while (0)

#define G_EPILOGUE()                                                             \
    _Pragma("unroll")                                                            \
    for (int mt = 0; mt < 4; mt++) {                                             \
        _Pragma("unroll")                                                        \
        for (int nt = 0; nt < 4; nt++) {                                         \
            int row = m0 + wm*64 + mt*16 + lr;                                   \
            int col = n0 + wn*32 + nt*8 + 2*lc;                                  \
            float bx = 0.f, by = 0.f;                                            \
            if (bias) { bx = bias[col]; by = bias[col + 1]; }                    \
            *(float2*)(C + (size_t)row * Dm + col) =                             \
                make_float2(acc[mt][nt][0] + bx, acc[mt][nt][1] + by);           \
            *(float2*)(C + (size_t)(row + 8) * Dm + col) =                       \
                make_float2(acc[mt][nt][2] + bx, acc[mt][nt][3] + by);           \
        }                                                                        \
    }

// ---- tf32 3-product core, B streamed from W[h][d][e] as [k][n] tiles ----
// (Q/K projections: argmax-critical). n-tile (64) == one head.
__device__ __forceinline__ void gemm_core_tf32_bt(
    const float* __restrict__ A1, const float* __restrict__ Wh,
    float* __restrict__ C, int m0, int n0, float* sm)
{
    const float* A2 = A1; const int K1 = Dm, K = Dm;
    const float* bias = nullptr;
    float* Abuf[2] = { sm,              sm + 128*GPAD };
    float* Bbuf[2] = { sm + 2*128*GPAD, sm + 2*128*GPAD + 32*BTPAD };
    const int tid = threadIdx.x;
    const int wid = tid >> 5, lane = tid & 31;
    const int wm = wid & 1, wn = wid >> 1;
    const int lr = lane >> 2, lc = lane & 3;
    const int NC = K / 32;

#define B_LOAD_BT(buf, k0_) do {                                                 \
        int k0 = (k0_);                                                          \
        _Pragma("unroll")                                                        \
        for (int i = 0; i < 4; i++) {                                            \
            int id = tid + i * 128;                                              \
            int kk = id >> 4, n4 = (id & 15) * 4;                                \
            cp_async16(Bbuf[buf] + kk*BTPAD + n4,                                \
                       Wh + (size_t)(k0 + kk)*64 + n4);                          \
        }                                                                         \
    } while (0)

    A_LOAD(0, 0); B_LOAD_BT(0, 0); CP_COMMIT();
    A_LOAD(1, 32); B_LOAD_BT(1, 32); CP_COMMIT();

    float acc[4][4][4];
#pragma unroll
    for (int a = 0; a < 4; a++)
#pragma unroll
        for (int b = 0; b < 4; b++)
#pragma unroll
            for (int c = 0; c < 4; c++) acc[a][b][c] = 0.f;

    for (int c = 0; c < NC; c++) {
        if (c < NC - 1) CP_WAIT1(); else CP_WAIT0();
        __syncthreads();
        const int buf = c & 1;
        const float* Ab = Abuf[buf] + wm * 64 * GPAD;
        const float* Bb = Bbuf[buf];
#pragma unroll
        for (int ks = 0; ks < 4; ks++) {
            const int kb = ks * 8 + lc;
            uint32_t bh[4][2], bl[4][2];
#pragma unroll
            for (int nt = 0; nt < 4; nt++) {
                int nl = wn*32 + nt*8 + lr;
                splitf(Bb[kb*BTPAD + nl],       bh[nt][0], bl[nt][0]);
                splitf(Bb[(kb+4)*BTPAD + nl],   bh[nt][1], bl[nt][1]);
            }
#pragma unroll
            for (int mt = 0; mt < 4; mt++) {
                uint32_t ah[4], al[4];
                splitf(Ab[(mt*16 + lr    )*GPAD + kb],     ah[0], al[0]);
                splitf(Ab[(mt*16 + lr + 8)*GPAD + kb],     ah[1], al[1]);
                splitf(Ab[(mt*16 + lr    )*GPAD + kb + 4], ah[2], al[2]);
                splitf(Ab[(mt*16 + lr + 8)*GPAD + kb + 4], ah[3], al[3]);
#pragma unroll
                for (int nt = 0; nt < 4; nt++) {
                    mma8(acc[mt][nt], ah, bh[nt]);
                    mma8(acc[mt][nt], ah, bl[nt]);
                    mma8(acc[mt][nt], al, bh[nt]);
                }
            }
        }
        __syncthreads();
        if (c + 2 < NC) { A_LOAD(buf, (c + 2) * 32); B_LOAD_BT(buf, (c + 2) * 32); CP_COMMIT(); }
    }
    G_EPILOGUE()
#undef B_LOAD_BT
}

// ---- bf16 split 3-product core, B from W[h][d][e] as [k][n] tiles (V proj) ----
__device__ __forceinline__ void gemm_core_bf_bt(
    const float* __restrict__ A1, const float* __restrict__ Wh,
    float* __restrict__ C, int m0, int n0, float* sm)
{
    const float* A2 = A1; const int K1 = Dm, K = Dm;
    const float* bias = nullptr;
    float* Abuf[2] = { sm,              sm + 128*GPAD };
    float* Bbuf[2] = { sm + 2*128*GPAD, sm + 2*128*GPAD + 32*BTPAD };
    const int tid = threadIdx.x;
    const int wid = tid >> 5, lane = tid & 31;
    const int wm = wid & 1, wn = wid >> 1;
    const int lr = lane >> 2, lc = lane & 3;
    const int NC = K / 32;

#define B_LOAD_BT(buf, k0_) do {                                                 \
        int k0 = (k0_);                                                          \
        _Pragma("unroll")                                                        \
        for (int i = 0; i < 4; i++) {                                            \
            int id = tid + i * 128;                                              \
            int kk = id >> 4, n4 = (id & 15) * 4;                                \
            cp_async16(Bbuf[buf] + kk*BTPAD + n4,                                \
                       Wh + (size_t)(k0 + kk)*64 + n4);                          \
        }                                                                         \
    } while (0)

    A_LOAD(0, 0); B_LOAD_BT(0, 0); CP_COMMIT();
    A_LOAD(1, 32); B_LOAD_BT(1, 32); CP_COMMIT();

    float acc[4][4][4];
#pragma unroll
    for (int a = 0; a < 4; a++)
#pragma unroll
        for (int b = 0; b < 4; b++)
#pragma unroll
            for (int c = 0; c < 4; c++) acc[a][b][c] = 0.f;

    for (int c = 0; c < NC; c++) {
        if (c < NC - 1) CP_WAIT1(); else CP_WAIT0();
        __syncthreads();
        const int buf = c & 1;
        const float* Ab = Abuf[buf] + wm * 64 * GPAD;
        const float* Bb = Bbuf[buf];
#pragma unroll
        for (int ks = 0; ks < 2; ks++) {
            const int kb = ks * 16 + 2 * lc;
            uint32_t bh[4][2], bl[4][2];
#pragma unroll
            for (int nt = 0; nt < 4; nt++) {
                int nl = wn*32 + nt*8 + lr;
                split2(Bb[kb*BTPAD + nl],     Bb[(kb+1)*BTPAD + nl], bh[nt][0], bl[nt][0]);
                split2(Bb[(kb+8)*BTPAD + nl], Bb[(kb+9)*BTPAD + nl], bh[nt][1], bl[nt][1]);
            }
#pragma unroll
            for (int mt = 0; mt < 4; mt++) {
                uint32_t ah[4], al[4];
                float2 a00 = *(const float2*)(Ab + (mt*16 + lr    )*GPAD + kb);
                float2 a10 = *(const float2*)(Ab + (mt*16 + lr + 8)*GPAD + kb);
                float2 a01 = *(const float2*)(Ab + (mt*16 + lr    )*GPAD + kb + 8);
                float2 a11 = *(const float2*)(Ab + (mt*16 + lr + 8)*GPAD + kb + 8);
                split2(a00.x, a00.y, ah[0], al[0]);
                split2(a10.x, a10.y, ah[1], al[1]);
                split2(a01.x, a01.y, ah[2], al[2]);
                split2(a11.x, a11.y, ah[3], al[3]);
#pragma unroll
                for (int nt = 0; nt < 4; nt++) {
                    mma16(acc[mt][nt], ah, bh[nt]);
                    mma16(acc[mt][nt], ah, bl[nt]);
                    mma16(acc[mt][nt], al, bh[nt]);
                }
            }
        }
        __syncthreads();
        if (c + 2 < NC) { A_LOAD(buf, (c + 2) * 32); B_LOAD_BT(buf, (c + 2) * 32); CP_COMMIT(); }
    }
    G_EPILOGUE()
#undef B_LOAD_BT
}

// ---- bf16 split 3-product core, B = [n][k] row-major weights (proj/lin) ----
__device__ __forceinline__ void gemm_core_bf(
    const float* __restrict__ A1, const float* __restrict__ A2, int K1, int K,
    const float* __restrict__ Bm, const float* __restrict__ bias,
    float* __restrict__ C, int m0, int n0, float* sm)
{
    float* Abuf[2] = { sm,              sm + 128*GPAD };
    float* Bbuf[2] = { sm + 2*128*GPAD, sm + 2*128*GPAD + 64*GPAD };
    const int tid = threadIdx.x;
    const int wid = tid >> 5, lane = tid & 31;
    const int wm = wid & 1, wn = wid >> 1;
    const int lr = lane >> 2, lc = lane & 3;
    const int NC = K / 32;

#define B_LOAD_NK(buf, k0_) do {                                                 \
        int k0 = (k0_);                                                          \
        _Pragma("unroll")                                                        \
        for (int i = 0; i < 4; i++) {                                            \
            int id = tid + i * 128;                                              \
            int row = id >> 3, c4 = (id & 7) * 4;                                \
            cp_async16(Bbuf[buf] + row*GPAD + c4,                                \
                       Bm + (size_t)(n0 + row)*K + k0 + c4);                     \
        }                                                                         \
    } while (0)

    A_LOAD(0, 0); B_LOAD_NK(0, 0); CP_COMMIT();
    A_LOAD(1, 32); B_LOAD_NK(1, 32); CP_COMMIT();

    float acc[4][4][4];
#pragma unroll
    for (int a = 0; a < 4; a++)
#pragma unroll
        for (int b = 0; b < 4; b++)
#pragma unroll
            for (int c = 0; c < 4; c++) acc[a][b][c] = 0.f;

    for (int c = 0; c < NC; c++) {
        if (c < NC - 1) CP_WAIT1(); else CP_WAIT0();
        __syncthreads();
        const int buf = c & 1;
        const float* Ab = Abuf[buf] + wm * 64 * GPAD;
        const float* Bb = Bbuf[buf] + wn * 32 * GPAD;
#pragma unroll
        for (int ks = 0; ks < 2; ks++) {
            const int kb = ks * 16 + 2 * lc;
            uint32_t bh[4][2], bl[4][2];
#pragma unroll
            for (int nt = 0; nt < 4; nt++) {
                float2 b0 = *(const float2*)(Bb + (nt*8 + lr)*GPAD + kb);
                float2 b1 = *(const float2*)(Bb + (nt*8 + lr)*GPAD + kb + 8);
                split2(b0.x, b0.y, bh[nt][0], bl[nt][0]);
                split2(b1.x, b1.y, bh[nt][1], bl[nt][1]);
            }
#pragma unroll
            for (int mt = 0; mt < 4; mt++) {
                uint32_t ah[4], al[4];
                float2 a00 = *(const float2*)(Ab + (mt*16 + lr    )*GPAD + kb);
                float2 a10 = *(const float2*)(Ab + (mt*16 + lr + 8)*GPAD + kb);
                float2 a01 = *(const float2*)(Ab + (mt*16 + lr    )*GPAD + kb + 8);
                float2 a11 = *(const float2*)(Ab + (mt*16 + lr + 8)*GPAD + kb + 8);
                split2(a00.x, a00.y, ah[0], al[0]);
                split2(a10.x, a10.y, ah[1], al[1]);
                split2(a01.x, a01.y, ah[2], al[2]);
                split2(a11.x, a11.y, ah[3], al[3]);
#pragma unroll
                for (int nt = 0; nt < 4; nt++) {
                    mma16(acc[mt][nt], ah, bh[nt]);
                    mma16(acc[mt][nt], ah, bl[nt]);
                    mma16(acc[mt][nt], al, bh[nt]);
                }
            }
        }
        __syncthreads();
        if (c + 2 < NC) { A_LOAD(buf, (c + 2) * 32); B_LOAD_NK(buf, (c + 2) * 32); CP_COMMIT(); }
    }
    G_EPILOGUE()
#undef B_LOAD_NK
}

// Fused Q/K/V projections: z=0 Q (tf32), z=1 K (tf32), z=2 V (bf16).
// blockIdx.x = head; weights read in-place ([k][n] layout in gmem).
__global__ __launch_bounds__(128, 3) void qkv_mma_bt(
    const float* __restrict__ qd, const float* __restrict__ kd, const float* __restrict__ vd,
    const float* __restrict__ wq, const float* __restrict__ wk, const float* __restrict__ wv)
{
    extern __shared__ float sm[];
    const int z = blockIdx.z;
    if (z == 2) {
        gemm_core_bf_bt(vd, wv + (size_t)blockIdx.x * Dm * 64, g_vs,
                        blockIdx.y * 128, blockIdx.x * 64, sm);
    } else {
        const float* A = (z == 0) ? qd : kd;
        const float* W = ((z == 0) ? wq : wk) + (size_t)blockIdx.x * Dm * 64;
        float* C = (z == 0) ? g_qs : g_ks;
        gemm_core_tf32_bt(A, W, C, blockIdx.y * 128, blockIdx.x * 64, sm);
    }
}

__global__ __launch_bounds__(128, 3) void gemm_bf_mma(
    const float* __restrict__ A1, const float* __restrict__ A2, int K1, int K,
    const float* __restrict__ Bm, const float* __restrict__ bias, float* __restrict__ C)
{
    extern __shared__ float sm[];
    gemm_core_bf(A1, A2, K1, K, Bm, bias, C, blockIdx.y * 128, blockIdx.x * 64, sm);
}

// ============================================================================
// QK^T + softmax stats + dense attn-output fill (zeros + scatter) fused.
// CTA = (h, b, 128 q rows); streams 16 K-tiles of 64 rows; raw-sum softmax
// with MUFU ex2 (no FMA-pipe polynomial), explicit max/argmax compare.
// ============================================================================
#define APAD 68
#define S_SMEM ((128*APAD + 2*64*APAD)*4 + 256*4*3)  /* 72704 */
__global__ __launch_bounds__(128, 3) void attn_stats_mma(float* __restrict__ attn)
{
    extern __shared__ float sm[];
    float* Qs   = sm;
    float* Kbuf[2] = { sm + 128*APAD, sm + 128*APAD + 64*APAD };
    float* redm = sm + 128*APAD + 2*64*APAD;
    float* reds = redm + 256;
    int*   redi = (int*)(reds + 256);

    const int tid = threadIdx.x;
    const int h = blockIdx.z, b = blockIdx.y, q0 = blockIdx.x * 128;
    const int wid = tid >> 5, lane = tid & 31;
    const int wm = wid & 1, wn = wid >> 1;
    const int lr = lane >> 2, lc = lane & 3;

    const float* Qg = g_qs + ((size_t)(b * Ls + q0)) * Dm + h * 64;
    const float* Kg = g_ks + ((size_t)(b * Ls)) * Dm + h * 64;
    const size_t rowbase = (size_t)(h * Bn + b) * Ls + q0;   // attn row base

#pragma unroll
    for (int i = 0; i < 16; i++) {
        int id = tid + i * 128;
        int row = id >> 4, c4 = (id & 15) * 4;
        cp_async16(Qs + row*APAD + c4, Qg + (size_t)row * Dm + c4);
    }
    CP_COMMIT();

#define K_LOAD(buf, t_) do {                                                    \
        _Pragma("unroll")                                                       \
        for (int i = 0; i < 8; i++) {                                           \
            int id = tid + i * 128;                                             \
            int row = id >> 4, c4 = (id & 15) * 4;                              \
            cp_async16(Kbuf[buf] + row*APAD + c4,                               \
                       Kg + (size_t)((t_)*64 + row) * Dm + c4);                 \
        }                                                                       \
    } while (0)

    K_LOAD(0, 0); CP_COMMIT();
    K_LOAD(1, 1); CP_COMMIT();

    float rm[8], rs[8];
    int ridx[8];
#pragma unroll
    for (int i = 0; i < 8; i++) { rm[i] = -1e30f; rs[i] = 0.f; ridx[i] = 0; }

    for (int t = 0; t < 16; t++) {
        if (t < 15) CP_WAIT1(); else CP_WAIT0();
        __syncthreads();
        const int buf = t & 1;
        const float* Ab = Qs + wm * 64 * APAD;
        const float* Bb = Kbuf[buf] + wn * 32 * APAD;

        float acc[4][4][4];
#pragma unroll
        for (int a = 0; a < 4; a++)
#pragma unroll
            for (int bb = 0; bb < 4; bb++)
#pragma unroll
                for (int cc = 0; cc < 4; cc++) acc[a][bb][cc] = 0.f;

#pragma unroll
        for (int ks = 0; ks < 8; ks++) {
            const int kb = ks * 8 + lc;
            uint32_t bh[4][2], bl[4][2];
#pragma unroll
            for (int nt = 0; nt < 4; nt++) {
                splitf(Bb[(nt*8 + lr)*APAD + kb],     bh[nt][0], bl[nt][0]);
                splitf(Bb[(nt*8 + lr)*APAD + kb + 4], bh[nt][1], bl[nt][1]);
            }
#pragma unroll
            for (int mt = 0; mt < 4; mt++) {
                uint32_t ah[4], al[4];
                splitf(Ab[(mt*16 + lr    )*APAD + kb],     ah[0], al[0]);
                splitf(Ab[(mt*16 + lr + 8)*APAD + kb],     ah[1], al[1]);
                splitf(Ab[(mt*16 + lr    )*APAD + kb + 4], ah[2], al[2]);
                splitf(Ab[(mt*16 + lr + 8)*APAD + kb + 4], ah[3], al[3]);
#pragma unroll
                for (int nt = 0; nt < 4; nt++) {
                    mma8(acc[mt][nt], ah, bh[nt]);
                    mma8(acc[mt][nt], ah, bl[nt]);
                    mma8(acc[mt][nt], al, bh[nt]);
                }
            }
        }

        // streaming zero-fill of this CTA's attn slice, s-range [t*64, t*64+64)
        {
            float4 z4 = make_float4(0.f, 0.f, 0.f, 0.f);
#pragma unroll
            for (int i = 0; i < 16; i++) {
                int id = tid + i * 128;
                int r = id >> 4, f4 = id & 15;
                __stcs((float4*)(attn + (rowbase + r) * Ls + t * 64 + f4 * 4), z4);
            }
        }

        // fold tile into per-thread stats (raw sum via MUFU ex2 + explicit argmax)
        const int sbase = t * 64 + wn * 32 + 2 * lc;
#pragma unroll
        for (int mt = 0; mt < 4; mt++) {
#pragma unroll
            for (int half = 0; half < 2; half++) {
                const int r8 = mt * 2 + half;
                float m = rm[r8], s_ = rs[r8];
                int id_ = ridx[r8];
#pragma unroll
                for (int nt = 0; nt < 4; nt++) {
#pragma unroll
                    for (int j = 0; j < 2; j++) {
                        float v = acc[mt][nt][half*2 + j];
                        if (v > m) { m = v; id_ = sbase + nt*8 + j; }
                        s_ += fex2(v * CC);
                    }
                }
                rm[r8] = m; rs[r8] = s_; ridx[r8] = id_;
            }
        }
        __syncthreads();
        if (t + 2 < 16) { K_LOAD(buf, t + 2); CP_COMMIT(); }
    }

    // quad reduce over lc (same rows, different cols)
#pragma unroll
    for (int r8 = 0; r8 < 8; r8++) {
        float m = rm[r8], s_ = rs[r8];
        int id_ = ridx[r8];
#pragma unroll
        for (int off = 1; off <= 2; off <<= 1) {
            float om = __shfl_xor_sync(0xffffffffu, m, off);
            float os = __shfl_xor_sync(0xffffffffu, s_, off);
            int   oi = __shfl_xor_sync(0xffffffffu, id_, off);
            s_ += os;
            if (om > m) { m = om; id_ = oi; }
        }
        if (lc == 0) {
            int rowl = wm*64 + (r8 >> 1)*16 + (r8 & 1)*8 + lr;
            redm[rowl*2 + wn] = m;
            reds[rowl*2 + wn] = s_;
            redi[rowl*2 + wn] = id_;
        }
    }
    __syncthreads();   // also orders all zero-fill stores before the scatter below

    {
        float m = redm[tid*2], s_ = reds[tid*2];
        int id_ = redi[tid*2];
        float om = redm[tid*2 + 1];
        s_ += reds[tid*2 + 1];
        if (om > m) { m = om; id_ = redi[tid*2 + 1]; }
        float p = fex2(m * CC) / s_;
        int row = (int)(rowbase) + tid;
        g_p[row] = p;
        g_amax[row] = id_;
        attn[(rowbase + tid) * Ls + id_] = p;     // scatter the single nonzero
    }
#undef K_LOAD
}

// ============================================================================
// attn @ V collapsed to a vectorized gather
// ============================================================================
__global__ void gather_kernel()
{
    int idx4 = blockIdx.x * blockDim.x + threadIdx.x;   // over M_ALL*Dm/4
    if (idx4 >= M_ALL * Dm / 4) return;
    int e4 = idx4 & 15;            // 16 float4 per head
    int h  = (idx4 >> 4) & 7;
    int m  = idx4 >> 7;            // b*L + q
    int b  = m >> 10;
    int q  = m & 1023;
    int row = (h * Bn + b) * Ls + q;
    float p = g_p[row];
    int   s = g_amax[row];
    float4 v = *(const float4*)(g_vs + ((size_t)(b * Ls + s)) * Dm + h * 64 + e4 * 4);
    v.x *= p; v.y *= p; v.z *= p; v.w *= p;
    *(float4*)(g_headout + (size_t)idx4 * 4) = v;
}

// ============================================================================
extern "C" void kernel_launch(void* const* d_in, const int* in_sizes, int n_in,
                              void* d_out, int out_size)
{
    const float* q_data = (const float*)d_in[0];
    const float* k_data = (const float*)d_in[1];
    const float* v_data = (const float*)d_in[2];
    const float* w_qs   = (const float*)d_in[3];
    const float* w_ks   = (const float*)d_in[4];
    const float* w_vs   = (const float*)d_in[5];
    const float* proj_w = (const float*)d_in[6];
    const float* proj_b = (const float*)d_in[7];
    const float* lin_w  = (const float*)d_in[8];
    const float* lin_b  = (const float*)d_in[9];

    float* out  = (float*)d_out;                    // [B, L, D]
    float* attn = out + OUT_ELEMS;                  // [H*B, L, L]

    float *p_ho, *p_po;
    cudaGetSymbolAddress((void**)&p_ho, g_headout);
    cudaGetSymbolAddress((void**)&p_po, g_projout);

    cudaFuncSetAttribute(qkv_mma_bt, cudaFuncAttributeMaxDynamicSharedMemorySize, G_SMEM_BT);
    cudaFuncSetAttribute(gemm_bf_mma, cudaFuncAttributeMaxDynamicSharedMemorySize, G_SMEM);
    cudaFuncSetAttribute(attn_stats_mma, cudaFuncAttributeMaxDynamicSharedMemorySize, S_SMEM);

    // 1) Q/K/V projections fused into one launch (Q,K tf32; V bf16)
    qkv_mma_bt<<<dim3(8, 128, 3), 128, G_SMEM_BT>>>(q_data, k_data, v_data,
                                                    w_qs, w_ks, w_vs);

    // 2) QK^T + softmax stats + full dense attn-output fill (fused)
    attn_stats_mma<<<dim3(8, 16, 8), 128, S_SMEM>>>(attn);

    // 3) attn @ V collapsed to gather (vectorized)
    gather_kernel<<<(M_ALL * Dm / 4 + 255) / 256, 256>>>();

    // 4) output projection (bf16)
    gemm_bf_mma<<<dim3(8, 128), 128, G_SMEM>>>(p_ho, p_ho, Dm, Dm, proj_w, proj_b, p_po);

    // 5) final linear (bf16): out = [q_data | projout] @ lin_w^T + lin_b
    gemm_bf_mma<<<dim3(8, 128), 128, G_SMEM>>>(q_data, p_po, Dm, 2*Dm, lin_w, lin_b, out);
}

// round 9
// speedup vs baseline: 1.3600x; 1.1964x over previous
#include <cuda_runtime.h>
#include <cuda_fp16.h>
#include <cstdint>

#define Hh 8
#define Bn 16
#define Ls 1024
#define Dm 512
#define M_ALL (Bn*Ls)              /* 16384 */
#define OUT_ELEMS (Bn*Ls*Dm)       /* 8388608 */
#define NROWS (Hh*Bn*Ls)           /* 131072 */
// scores computed at 65536x scale (256 per operand); CCH = (1/sqrt(512))*log2(e)/65536
#define CCH  9.728829e-7f
#define UNSC 1.52587890625e-5f     /* 2^-16 */

// ---------------- static device scratch ----------------
__device__ float g_qs[M_ALL*Dm];        // [m][h*64+e]
__device__ float g_ks[M_ALL*Dm];
__device__ float g_vs[M_ALL*Dm];
__device__ float g_headout[M_ALL*Dm];   // [m][h*64+e]
__device__ float g_projout[M_ALL*Dm];
__device__ float g_p[NROWS];
__device__ int   g_amax[NROWS];

// ---------------- helpers ----------------
__device__ __forceinline__ uint32_t smem_u32(const void* p) {
    uint32_t a;
    asm("{ .reg .u64 t; cvta.to.shared.u64 t, %1; cvt.u32.u64 %0, t; }" : "=r"(a) : "l"(p));
    return a;
}
__device__ __forceinline__ void cp_async16(void* sdst, const void* gsrc) {
    uint32_t s = smem_u32(sdst);
    asm volatile("cp.async.ca.shared.global [%0], [%1], 16;" :: "r"(s), "l"(gsrc));
}
#define CP_COMMIT() asm volatile("cp.async.commit_group;" ::: "memory")
#define CP_WAIT1()  asm volatile("cp.async.wait_group 1;" ::: "memory")
#define CP_WAIT0()  asm volatile("cp.async.wait_group 0;" ::: "memory")

// bf16 pair split (magnitude-only paths)
__device__ __forceinline__ void split2(float x0, float x1, uint32_t& hi, uint32_t& lo) {
    uint32_t h;
    asm("cvt.rn.bf16x2.f32 %0, %1, %2;" : "=r"(h) : "f"(x1), "f"(x0));
    float h0 = __uint_as_float(h << 16);
    float h1 = __uint_as_float(h & 0xffff0000u);
    float r0 = x0 - h0, r1 = x1 - h1;
    asm("cvt.rn.bf16x2.f32 %0, %1, %2;" : "=r"(lo) : "f"(r1), "f"(r0));
    hi = h;
}
// fp16 pair split with x256 prescale (argmax-critical paths; residuals kept
// out of the fp16 denormal range so tensor-core FTZ behavior is irrelevant)
__device__ __forceinline__ void split2h(float x0, float x1, uint32_t& hi, uint32_t& lo) {
    x0 *= 256.f; x1 *= 256.f;
    __half2 h = __floats2half2_rn(x0, x1);          // low = x0, high = x1
    float f0 = __half2float(__low2half(h));
    float f1 = __half2float(__high2half(h));
    __half2 l = __floats2half2_rn(x0 - f0, x1 - f1);
    hi = *(uint32_t*)&h;
    lo = *(uint32_t*)&l;
}
// bf16 mma m16n8k16
__device__ __forceinline__ void mma16(float* d, const uint32_t* a, const uint32_t* b) {
    asm volatile("mma.sync.aligned.m16n8k16.row.col.f32.bf16.bf16.f32 "
                 "{%0,%1,%2,%3}, {%4,%5,%6,%7}, {%8,%9}, {%0,%1,%2,%3};"
                 : "+f"(d[0]), "+f"(d[1]), "+f"(d[2]), "+f"(d[3])
                 : "r"(a[0]), "r"(a[1]), "r"(a[2]), "r"(a[3]),
                   "r"(b[0]), "r"(b[1]));
}
// fp16 mma m16n8k16 (same fragment layout)
__device__ __forceinline__ void mma16h(float* d, const uint32_t* a, const uint32_t* b) {
    asm volatile("mma.sync.aligned.m16n8k16.row.col.f32.f16.f16.f32 "
                 "{%0,%1,%2,%3}, {%4,%5,%6,%7}, {%8,%9}, {%0,%1,%2,%3};"
                 : "+f"(d[0]), "+f"(d[1]), "+f"(d[2]), "+f"(d[3])
                 : "r"(a[0]), "r"(a[1]), "r"(a[2]), "r"(a[3]),
                   "r"(b[0]), "r"(b[1]));
}
// hardware exp2 (MUFU)
__device__ __forceinline__ float fex2(float z) {
    float r;
    asm("ex2.approx.f32 %0, %1;" : "=f"(r) : "f"(z));
    return r;
}

// ============================================================================
// GEMM scaffolding: 128(M) x 64(N) CTA tile, 128 thr = 4 warps 2(M)x2(N),
// warp tile 64x32, K chunks of 32, cp.async double buffer, 3 CTAs/SM.
// ============================================================================
#define GPAD 36
#define BTPAD 68
#define G_SMEM ((2*128*GPAD + 2*64*GPAD)*4)       /* 55296: [n][k]-weights form */
#define G_SMEM_BT ((2*128*GPAD + 2*32*BTPAD)*4)   /* 54272: [k][n]-weights form */

#define A_LOAD(buf, k0_) do {                                                    \
        int k0 = (k0_);                                                          \
        const float* Asrc; int lda, kc;                                          \
        if (k0 < K1) { Asrc = A1; lda = K1;     kc = k0; }                       \
        else         { Asrc = A2; lda = K - K1; kc = k0 - K1; }                  \
        _Pragma("unroll")                                                        \
        for (int i = 0; i < 8; i++) {                                            \
            int id = tid + i * 128;                                              \
            int row = id >> 3, c4 = (id & 7) * 4;                                \
            cp_async16(Abuf[buf] + row*GPAD + c4,                                \
                       Asrc + (size_t)(m0 + row)*lda + kc + c4);                 \
        }                                                                         \
    } while (0)

#define G_EPILOGUE()                                                             \
    _Pragma("unroll")                                                            \
    for (int mt = 0; mt < 4; mt++) {                                             \
        _Pragma("unroll")                                                        \
        for (int nt = 0; nt < 4; nt++) {                                         \
            int row = m0 + wm*64 + mt*16 + lr;                                   \
            int col = n0 + wn*32 + nt*8 + 2*lc;                                  \
            float bx = 0.f, by = 0.f;                                            \
            if (bias) { bx = bias[col]; by = bias[col + 1]; }                    \
            *(float2*)(C + (size_t)row * Dm + col) =                             \
                make_float2(acc[mt][nt][0] + bx, acc[mt][nt][1] + by);           \
            *(float2*)(C + (size_t)(row + 8) * Dm + col) =                       \
                make_float2(acc[mt][nt][2] + bx, acc[mt][nt][3] + by);           \
        }                                                                        \
    }

// scaled epilogue (fp16 cores: undo the 2^16 operand prescale), no bias
#define G_EPILOGUE_SCL()                                                         \
    _Pragma("unroll")                                                            \
    for (int mt = 0; mt < 4; mt++) {                                             \
        _Pragma("unroll")                                                        \
        for (int nt = 0; nt < 4; nt++) {                                         \
            int row = m0 + wm*64 + mt*16 + lr;                                   \
            int col = n0 + wn*32 + nt*8 + 2*lc;                                  \
            *(float2*)(C + (size_t)row * Dm + col) =                             \
                make_float2(acc[mt][nt][0]*UNSC, acc[mt][nt][1]*UNSC);           \
            *(float2*)(C + (size_t)(row + 8) * Dm + col) =                       \
                make_float2(acc[mt][nt][2]*UNSC, acc[mt][nt][3]*UNSC);           \
        }                                                                        \
    }

#define ACC_INIT() float acc[4][4][4];                                           \
    _Pragma("unroll") for (int a_ = 0; a_ < 4; a_++)                             \
    _Pragma("unroll") for (int b_ = 0; b_ < 4; b_++)                             \
    _Pragma("unroll") for (int c_ = 0; c_ < 4; c_++) acc[a_][b_][c_] = 0.f;

#define B_LOAD_BT(buf, k0_) do {                                                 \
        int k0 = (k0_);                                                          \
        _Pragma("unroll")                                                        \
        for (int i = 0; i < 4; i++) {                                            \
            int id = tid + i * 128;                                              \
            int kk = id >> 4, n4 = (id & 15) * 4;                                \
            cp_async16(Bbuf[buf] + kk*BTPAD + n4,                                \
                       Wh + (size_t)(k0 + kk)*64 + n4);                          \
        }                                                                         \
    } while (0)

// ---- fp16 3-product core, B from W[h][d][e] as [k][n] tiles (Q/K proj) ----
__device__ __forceinline__ void gemm_core_f16_bt(
    const float* __restrict__ A1, const float* __restrict__ Wh,
    float* __restrict__ C, int m0, int n0, float* sm)
{
    const float* A2 = A1; const int K1 = Dm, K = Dm;
    float* Abuf[2] = { sm,              sm + 128*GPAD };
    float* Bbuf[2] = { sm + 2*128*GPAD, sm + 2*128*GPAD + 32*BTPAD };
    const int tid = threadIdx.x;
    const int wid = tid >> 5, lane = tid & 31;
    const int wm = wid & 1, wn = wid >> 1;
    const int lr = lane >> 2, lc = lane & 3;
    const int NC = K / 32;

    A_LOAD(0, 0); B_LOAD_BT(0, 0); CP_COMMIT();
    A_LOAD(1, 32); B_LOAD_BT(1, 32); CP_COMMIT();
    ACC_INIT()

    for (int c = 0; c < NC; c++) {
        if (c < NC - 1) CP_WAIT1(); else CP_WAIT0();
        __syncthreads();
        const int buf = c & 1;
        const float* Ab = Abuf[buf] + wm * 64 * GPAD;
        const float* Bb = Bbuf[buf];
#pragma unroll
        for (int ks = 0; ks < 2; ks++) {            // k16 steps
            const int kb = ks * 16 + 2 * lc;
            uint32_t bh[4][2], bl[4][2];
#pragma unroll
            for (int nt = 0; nt < 4; nt++) {
                int nl = wn*32 + nt*8 + lr;
                split2h(Bb[kb*BTPAD + nl],     Bb[(kb+1)*BTPAD + nl], bh[nt][0], bl[nt][0]);
                split2h(Bb[(kb+8)*BTPAD + nl], Bb[(kb+9)*BTPAD + nl], bh[nt][1], bl[nt][1]);
            }
#pragma unroll
            for (int mt = 0; mt < 4; mt++) {
                uint32_t ah[4], al[4];
                float2 a00 = *(const float2*)(Ab + (mt*16 + lr    )*GPAD + kb);
                float2 a10 = *(const float2*)(Ab + (mt*16 + lr + 8)*GPAD + kb);
                float2 a01 = *(const float2*)(Ab + (mt*16 + lr    )*GPAD + kb + 8);
                float2 a11 = *(const float2*)(Ab + (mt*16 + lr + 8)*GPAD + kb + 8);
                split2h(a00.x, a00.y, ah[0], al[0]);
                split2h(a10.x, a10.y, ah[1], al[1]);
                split2h(a01.x, a01.y, ah[2], al[2]);
                split2h(a11.x, a11.y, ah[3], al[3]);
#pragma unroll
                for (int nt = 0; nt < 4; nt++) {
                    mma16h(acc[mt][nt], ah, bh[nt]);
                    mma16h(acc[mt][nt], ah, bl[nt]);
                    mma16h(acc[mt][nt], al, bh[nt]);
                }
            }
        }
        __syncthreads();
        if (c + 2 < NC) { A_LOAD(buf, (c + 2) * 32); B_LOAD_BT(buf, (c + 2) * 32); CP_COMMIT(); }
    }
    G_EPILOGUE_SCL()
}

// ---- bf16 3-product core, B from W[h][d][e] as [k][n] tiles (V proj) ----
__device__ __forceinline__ void gemm_core_bf_bt(
    const float* __restrict__ A1, const float* __restrict__ Wh,
    float* __restrict__ C, int m0, int n0, float* sm)
{
    const float* A2 = A1; const int K1 = Dm, K = Dm;
    const float* bias = nullptr;
    float* Abuf[2] = { sm,              sm + 128*GPAD };
    float* Bbuf[2] = { sm + 2*128*GPAD, sm + 2*128*GPAD + 32*BTPAD };
    const int tid = threadIdx.x;
    const int wid = tid >> 5, lane = tid & 31;
    const int wm = wid & 1, wn = wid >> 1;
    const int lr = lane >> 2, lc = lane & 3;
    const int NC = K / 32;

    A_LOAD(0, 0); B_LOAD_BT(0, 0); CP_COMMIT();
    A_LOAD(1, 32); B_LOAD_BT(1, 32); CP_COMMIT();
    ACC_INIT()

    for (int c = 0; c < NC; c++) {
        if (c < NC - 1) CP_WAIT1(); else CP_WAIT0();
        __syncthreads();
        const int buf = c & 1;
        const float* Ab = Abuf[buf] + wm * 64 * GPAD;
        const float* Bb = Bbuf[buf];
#pragma unroll
        for (int ks = 0; ks < 2; ks++) {
            const int kb = ks * 16 + 2 * lc;
            uint32_t bh[4][2], bl[4][2];
#pragma unroll
            for (int nt = 0; nt < 4; nt++) {
                int nl = wn*32 + nt*8 + lr;
                split2(Bb[kb*BTPAD + nl],     Bb[(kb+1)*BTPAD + nl], bh[nt][0], bl[nt][0]);
                split2(Bb[(kb+8)*BTPAD + nl], Bb[(kb+9)*BTPAD + nl], bh[nt][1], bl[nt][1]);
            }
#pragma unroll
            for (int mt = 0; mt < 4; mt++) {
                uint32_t ah[4], al[4];
                float2 a00 = *(const float2*)(Ab + (mt*16 + lr    )*GPAD + kb);
                float2 a10 = *(const float2*)(Ab + (mt*16 + lr + 8)*GPAD + kb);
                float2 a01 = *(const float2*)(Ab + (mt*16 + lr    )*GPAD + kb + 8);
                float2 a11 = *(const float2*)(Ab + (mt*16 + lr + 8)*GPAD + kb + 8);
                split2(a00.x, a00.y, ah[0], al[0]);
                split2(a10.x, a10.y, ah[1], al[1]);
                split2(a01.x, a01.y, ah[2], al[2]);
                split2(a11.x, a11.y, ah[3], al[3]);
#pragma unroll
                for (int nt = 0; nt < 4; nt++) {
                    mma16(acc[mt][nt], ah, bh[nt]);
                    mma16(acc[mt][nt], ah, bl[nt]);
                    mma16(acc[mt][nt], al, bh[nt]);
                }
            }
        }
        __syncthreads();
        if (c + 2 < NC) { A_LOAD(buf, (c + 2) * 32); B_LOAD_BT(buf, (c + 2) * 32); CP_COMMIT(); }
    }
    G_EPILOGUE()
}

// ---- bf16 3-product core, B = [n][k] row-major weights (proj/lin) ----
__device__ __forceinline__ void gemm_core_bf(
    const float* __restrict__ A1, const float* __restrict__ A2, int K1, int K,
    const float* __restrict__ Bm, const float* __restrict__ bias,
    float* __restrict__ C, int m0, int n0, float* sm)
{
    float* Abuf[2] = { sm,              sm + 128*GPAD };
    float* Bbuf[2] = { sm + 2*128*GPAD, sm + 2*128*GPAD + 64*GPAD };
    const int tid = threadIdx.x;
    const int wid = tid >> 5, lane = tid & 31;
    const int wm = wid & 1, wn = wid >> 1;
    const int lr = lane >> 2, lc = lane & 3;
    const int NC = K / 32;

#define B_LOAD_NK(buf, k0_) do {                                                 \
        int k0 = (k0_);                                                          \
        _Pragma("unroll")                                                        \
        for (int i = 0; i < 4; i++) {                                            \
            int id = tid + i * 128;                                              \
            int row = id >> 3, c4 = (id & 7) * 4;                                \
            cp_async16(Bbuf[buf] + row*GPAD + c4,                                \
                       Bm + (size_t)(n0 + row)*K + k0 + c4);                     \
        }                                                                         \
    } while (0)

    A_LOAD(0, 0); B_LOAD_NK(0, 0); CP_COMMIT();
    A_LOAD(1, 32); B_LOAD_NK(1, 32); CP_COMMIT();
    ACC_INIT()

    for (int c = 0; c < NC; c++) {
        if (c < NC - 1) CP_WAIT1(); else CP_WAIT0();
        __syncthreads();
        const int buf = c & 1;
        const float* Ab = Abuf[buf] + wm * 64 * GPAD;
        const float* Bb = Bbuf[buf] + wn * 32 * GPAD;
#pragma unroll
        for (int ks = 0; ks < 2; ks++) {
            const int kb = ks * 16 + 2 * lc;
            uint32_t bh[4][2], bl[4][2];
#pragma unroll
            for (int nt = 0; nt < 4; nt++) {
                float2 b0 = *(const float2*)(Bb + (nt*8 + lr)*GPAD + kb);
                float2 b1 = *(const float2*)(Bb + (nt*8 + lr)*GPAD + kb + 8);
                split2(b0.x, b0.y, bh[nt][0], bl[nt][0]);
                split2(b1.x, b1.y, bh[nt][1], bl[nt][1]);
            }
#pragma unroll
            for (int mt = 0; mt < 4; mt++) {
                uint32_t ah[4], al[4];
                float2 a00 = *(const float2*)(Ab + (mt*16 + lr    )*GPAD + kb);
                float2 a10 = *(const float2*)(Ab + (mt*16 + lr + 8)*GPAD + kb);
                float2 a01 = *(const float2*)(Ab + (mt*16 + lr    )*GPAD + kb + 8);
                float2 a11 = *(const float2*)(Ab + (mt*16 + lr + 8)*GPAD + kb + 8);
                split2(a00.x, a00.y, ah[0], al[0]);
                split2(a10.x, a10.y, ah[1], al[1]);
                split2(a01.x, a01.y, ah[2], al[2]);
                split2(a11.x, a11.y, ah[3], al[3]);
#pragma unroll
                for (int nt = 0; nt < 4; nt++) {
                    mma16(acc[mt][nt], ah, bh[nt]);
                    mma16(acc[mt][nt], ah, bl[nt]);
                    mma16(acc[mt][nt], al, bh[nt]);
                }
            }
        }
        __syncthreads();
        if (c + 2 < NC) { A_LOAD(buf, (c + 2) * 32); B_LOAD_NK(buf, (c + 2) * 32); CP_COMMIT(); }
    }
    G_EPILOGUE()
#undef B_LOAD_NK
}

// Fused Q/K/V projections: z=0 Q (fp16x3), z=1 K (fp16x3), z=2 V (bf16x3).
__global__ __launch_bounds__(128, 3) void qkv_mma_bt(
    const float* __restrict__ qd, const float* __restrict__ kd, const float* __restrict__ vd,
    const float* __restrict__ wq, const float* __restrict__ wk, const float* __restrict__ wv)
{
    extern __shared__ float sm[];
    const int z = blockIdx.z;
    if (z == 2) {
        gemm_core_bf_bt(vd, wv + (size_t)blockIdx.x * Dm * 64, g_vs,
                        blockIdx.y * 128, blockIdx.x * 64, sm);
    } else {
        const float* A = (z == 0) ? qd : kd;
        const float* W = ((z == 0) ? wq : wk) + (size_t)blockIdx.x * Dm * 64;
        float* C = (z == 0) ? g_qs : g_ks;
        gemm_core_f16_bt(A, W, C, blockIdx.y * 128, blockIdx.x * 64, sm);
    }
}

__global__ __launch_bounds__(128, 3) void gemm_bf_mma(
    const float* __restrict__ A1, const float* __restrict__ A2, int K1, int K,
    const float* __restrict__ Bm, const float* __restrict__ bias, float* __restrict__ C)
{
    extern __shared__ float sm[];
    gemm_core_bf(A1, A2, K1, K, Bm, bias, C, blockIdx.y * 128, blockIdx.x * 64, sm);
}

// ============================================================================
// QK^T (fp16x3, operands prescaled x256) + softmax stats + dense attn fill.
// CTA = (h, b, 128 q rows); streams 16 K-tiles of 64 rows; raw-sum softmax
// with MUFU ex2 on scaled scores (CCH absorbs the 2^-16).
// ============================================================================
#define APAD 68
#define S_SMEM ((128*APAD + 2*64*APAD)*4 + 256*4*3)  /* 72704 */
__global__ __launch_bounds__(128, 3) void attn_stats_mma(float* __restrict__ attn)
{
    extern __shared__ float sm[];
    float* Qs   = sm;
    float* Kbuf[2] = { sm + 128*APAD, sm + 128*APAD + 64*APAD };
    float* redm = sm + 128*APAD + 2*64*APAD;
    float* reds = redm + 256;
    int*   redi = (int*)(reds + 256);

    const int tid = threadIdx.x;
    const int h = blockIdx.z, b = blockIdx.y, q0 = blockIdx.x * 128;
    const int wid = tid >> 5, lane = tid & 31;
    const int wm = wid & 1, wn = wid >> 1;
    const int lr = lane >> 2, lc = lane & 3;

    const float* Qg = g_qs + ((size_t)(b * Ls + q0)) * Dm + h * 64;
    const float* Kg = g_ks + ((size_t)(b * Ls)) * Dm + h * 64;
    const size_t rowbase = (size_t)(h * Bn + b) * Ls + q0;   // attn row base

#pragma unroll
    for (int i = 0; i < 16; i++) {
        int id = tid + i * 128;
        int row = id >> 4, c4 = (id & 15) * 4;
        cp_async16(Qs + row*APAD + c4, Qg + (size_t)row * Dm + c4);
    }
    CP_COMMIT();

#define K_LOAD(buf, t_) do {                                                    \
        _Pragma("unroll")                                                       \
        for (int i = 0; i < 8; i++) {                                           \
            int id = tid + i * 128;                                             \
            int row = id >> 4, c4 = (id & 15) * 4;                              \
            cp_async16(Kbuf[buf] + row*APAD + c4,                               \
                       Kg + (size_t)((t_)*64 + row) * Dm + c4);                 \
        }                                                                       \
    } while (0)

    K_LOAD(0, 0); CP_COMMIT();
    K_LOAD(1, 1); CP_COMMIT();

    float rm[8], rs[8];
    int ridx[8];
#pragma unroll
    for (int i = 0; i < 8; i++) { rm[i] = -1e30f; rs[i] = 0.f; ridx[i] = 0; }

    for (int t = 0; t < 16; t++) {
        if (t < 15) CP_WAIT1(); else CP_WAIT0();
        __syncthreads();
        const int buf = t & 1;
        const float* Ab = Qs + wm * 64 * APAD;
        const float* Bb = Kbuf[buf] + wn * 32 * APAD;

        ACC_INIT()

#pragma unroll
        for (int ks = 0; ks < 4; ks++) {            // dk=64 in 4 k16 steps
            const int kb = ks * 16 + 2 * lc;
            uint32_t bh[4][2], bl[4][2];
#pragma unroll
            for (int nt = 0; nt < 4; nt++) {
                float2 b0 = *(const float2*)(Bb + (nt*8 + lr)*APAD + kb);
                float2 b1 = *(const float2*)(Bb + (nt*8 + lr)*APAD + kb + 8);
                split2h(b0.x, b0.y, bh[nt][0], bl[nt][0]);
                split2h(b1.x, b1.y, bh[nt][1], bl[nt][1]);
            }
#pragma unroll
            for (int mt = 0; mt < 4; mt++) {
                uint32_t ah[4], al[4];
                float2 a00 = *(const float2*)(Ab + (mt*16 + lr    )*APAD + kb);
                float2 a10 = *(const float2*)(Ab + (mt*16 + lr + 8)*APAD + kb);
                float2 a01 = *(const float2*)(Ab + (mt*16 + lr    )*APAD + kb + 8);
                float2 a11 = *(const float2*)(Ab + (mt*16 + lr + 8)*APAD + kb + 8);
                split2h(a00.x, a00.y, ah[0], al[0]);
                split2h(a10.x, a10.y, ah[1], al[1]);
                split2h(a01.x, a01.y, ah[2], al[2]);
                split2h(a11.x, a11.y, ah[3], al[3]);
#pragma unroll
                for (int nt = 0; nt < 4; nt++) {
                    mma16h(acc[mt][nt], ah, bh[nt]);
                    mma16h(acc[mt][nt], ah, bl[nt]);
                    mma16h(acc[mt][nt], al, bh[nt]);
                }
            }
        }

        // streaming zero-fill of this CTA's attn slice, s-range [t*64, t*64+64)
        {
            float4 z4 = make_float4(0.f, 0.f, 0.f, 0.f);
#pragma unroll
            for (int i = 0; i < 16; i++) {
                int id = tid + i * 128;
                int r = id >> 4, f4 = id & 15;
                __stcs((float4*)(attn + (rowbase + r) * Ls + t * 64 + f4 * 4), z4);
            }
        }

        // fold tile into per-thread stats (raw sum via MUFU ex2 + explicit argmax)
        const int sbase = t * 64 + wn * 32 + 2 * lc;
#pragma unroll
        for (int mt = 0; mt < 4; mt++) {
#pragma unroll
            for (int half = 0; half < 2; half++) {
                const int r8 = mt * 2 + half;
                float m = rm[r8], s_ = rs[r8];
                int id_ = ridx[r8];
#pragma unroll
                for (int nt = 0; nt < 4; nt++) {
#pragma unroll
                    for (int j = 0; j < 2; j++) {
                        float v = acc[mt][nt][half*2 + j];
                        if (v > m) { m = v; id_ = sbase + nt*8 + j; }
                        s_ += fex2(v * CCH);
                    }
                }
                rm[r8] = m; rs[r8] = s_; ridx[r8] = id_;
            }
        }
        __syncthreads();
        if (t + 2 < 16) { K_LOAD(buf, t + 2); CP_COMMIT(); }
    }

    // quad reduce over lc (same rows, different cols)
#pragma unroll
    for (int r8 = 0; r8 < 8; r8++) {
        float m = rm[r8], s_ = rs[r8];
        int id_ = ridx[r8];
#pragma unroll
        for (int off = 1; off <= 2; off <<= 1) {
            float om = __shfl_xor_sync(0xffffffffu, m, off);
            float os = __shfl_xor_sync(0xffffffffu, s_, off);
            int   oi = __shfl_xor_sync(0xffffffffu, id_, off);
            s_ += os;
            if (om > m) { m = om; id_ = oi; }
        }
        if (lc == 0) {
            int rowl = wm*64 + (r8 >> 1)*16 + (r8 & 1)*8 + lr;
            redm[rowl*2 + wn] = m;
            reds[rowl*2 + wn] = s_;
            redi[rowl*2 + wn] = id_;
        }
    }
    __syncthreads();   // also orders all zero-fill stores before the scatter below

    {
        float m = redm[tid*2], s_ = reds[tid*2];
        int id_ = redi[tid*2];
        float om = redm[tid*2 + 1];
        s_ += reds[tid*2 + 1];
        if (om > m) { m = om; id_ = redi[tid*2 + 1]; }
        float p = fex2(m * CCH) / s_;
        int row = (int)(rowbase) + tid;
        g_p[row] = p;
        g_amax[row] = id_;
        attn[(rowbase + tid) * Ls + id_] = p;     // scatter the single nonzero
    }
#undef K_LOAD
}

// ============================================================================
// attn @ V collapsed to a vectorized gather
// ============================================================================
__global__ void gather_kernel()
{
    int idx4 = blockIdx.x * blockDim.x + threadIdx.x;   // over M_ALL*Dm/4
    if (idx4 >= M_ALL * Dm / 4) return;
    int e4 = idx4 & 15;            // 16 float4 per head
    int h  = (idx4 >> 4) & 7;
    int m  = idx4 >> 7;            // b*L + q
    int b  = m >> 10;
    int q  = m & 1023;
    int row = (h * Bn + b) * Ls + q;
    float p = g_p[row];
    int   s = g_amax[row];
    float4 v = *(const float4*)(g_vs + ((size_t)(b * Ls + s)) * Dm + h * 64 + e4 * 4);
    v.x *= p; v.y *= p; v.z *= p; v.w *= p;
    *(float4*)(g_headout + (size_t)idx4 * 4) = v;
}

// ============================================================================
extern "C" void kernel_launch(void* const* d_in, const int* in_sizes, int n_in,
                              void* d_out, int out_size)
{
    const float* q_data = (const float*)d_in[0];
    const float* k_data = (const float*)d_in[1];
    const float* v_data = (const float*)d_in[2];
    const float* w_qs   = (const float*)d_in[3];
    const float* w_ks   = (const float*)d_in[4];
    const float* w_vs   = (const float*)d_in[5];
    const float* proj_w = (const float*)d_in[6];
    const float* proj_b = (const float*)d_in[7];
    const float* lin_w  = (const float*)d_in[8];
    const float* lin_b  = (const float*)d_in[9];

    float* out  = (float*)d_out;                    // [B, L, D]
    float* attn = out + OUT_ELEMS;                  // [H*B, L, L]

    float *p_ho, *p_po;
    cudaGetSymbolAddress((void**)&p_ho, g_headout);
    cudaGetSymbolAddress((void**)&p_po, g_projout);

    cudaFuncSetAttribute(qkv_mma_bt, cudaFuncAttributeMaxDynamicSharedMemorySize, G_SMEM_BT);
    cudaFuncSetAttribute(gemm_bf_mma, cudaFuncAttributeMaxDynamicSharedMemorySize, G_SMEM);
    cudaFuncSetAttribute(attn_stats_mma, cudaFuncAttributeMaxDynamicSharedMemorySize, S_SMEM);

    // 1) Q/K/V projections fused into one launch (Q,K fp16x3; V bf16x3)
    qkv_mma_bt<<<dim3(8, 128, 3), 128, G_SMEM_BT>>>(q_data, k_data, v_data,
                                                    w_qs, w_ks, w_vs);

    // 2) QK^T + softmax stats + full dense attn-output fill (fused)
    attn_stats_mma<<<dim3(8, 16, 8), 128, S_SMEM>>>(attn);

    // 3) attn @ V collapsed to gather (vectorized)
    gather_kernel<<<(M_ALL * Dm / 4 + 255) / 256, 256>>>();

    // 4) output projection (bf16)
    gemm_bf_mma<<<dim3(8, 128), 128, G_SMEM>>>(p_ho, p_ho, Dm, Dm, proj_w, proj_b, p_po);

    // 5) final linear (bf16): out = [q_data | projout] @ lin_w^T + lin_b
    gemm_bf_mma<<<dim3(8, 128), 128, G_SMEM>>>(q_data, p_po, Dm, 2*Dm, lin_w, lin_b, out);
}

// round 10
// speedup vs baseline: 1.3810x; 1.0155x over previous
#include <cuda_runtime.h>
#include <cuda_fp16.h>
#include <cstdint>

#define Hh 8
#define Bn 16
#define Ls 1024
#define Dm 512
#define M_ALL (Bn*Ls)              /* 16384 */
#define OUT_ELEMS (Bn*Ls*Dm)       /* 8388608 */
#define NROWS (Hh*Bn*Ls)           /* 131072 */
// scores computed at 65536x scale; CCH = (1/sqrt(512))*log2(e)/65536
#define CCH  9.728829e-7f
#define UNSC 1.52587890625e-5f     /* 2^-16 */

// ---------------- static device scratch ----------------
// packed-pair layouts (uint32 = 2 halves, consecutive k):
//   g_q/g_k : [m][512] per head h: [h*64 + p] = hi pair p (0..31), [h*64+32+p] = lo  (fp16, x256)
//   g_ho/g_po/g_qd : [m][512] : [p] = hi pair p (0..255), [256+p] = lo               (bf16)
//   g_pw : [n][512] like above (K=512) ; g_lw : [n][1024] : hi 0..511, lo 512..1023  (bf16)
__device__ uint32_t g_q[M_ALL*512];
__device__ uint32_t g_k[M_ALL*512];
__device__ float    g_vs[M_ALL*Dm];
__device__ uint32_t g_ho[M_ALL*512];
__device__ uint32_t g_po[M_ALL*512];
__device__ uint32_t g_qd[M_ALL*512];
__device__ uint32_t g_pw[512*512];
__device__ uint32_t g_lw[512*1024];
__device__ float g_p[NROWS];
__device__ int   g_amax[NROWS];

// ---------------- helpers ----------------
__device__ __forceinline__ uint32_t smem_u32(const void* p) {
    uint32_t a;
    asm("{ .reg .u64 t; cvta.to.shared.u64 t, %1; cvt.u32.u64 %0, t; }" : "=r"(a) : "l"(p));
    return a;
}
__device__ __forceinline__ void cp_async16(void* sdst, const void* gsrc) {
    uint32_t s = smem_u32(sdst);
    asm volatile("cp.async.ca.shared.global [%0], [%1], 16;" :: "r"(s), "l"(gsrc));
}
#define CP_COMMIT() asm volatile("cp.async.commit_group;" ::: "memory")
#define CP_WAIT1()  asm volatile("cp.async.wait_group 1;" ::: "memory")
#define CP_WAIT0()  asm volatile("cp.async.wait_group 0;" ::: "memory")

// bf16 pair split
__device__ __forceinline__ void split2(float x0, float x1, uint32_t& hi, uint32_t& lo) {
    uint32_t h;
    asm("cvt.rn.bf16x2.f32 %0, %1, %2;" : "=r"(h) : "f"(x1), "f"(x0));
    float h0 = __uint_as_float(h << 16);
    float h1 = __uint_as_float(h & 0xffff0000u);
    float r0 = x0 - h0, r1 = x1 - h1;
    asm("cvt.rn.bf16x2.f32 %0, %1, %2;" : "=r"(lo) : "f"(r1), "f"(r0));
    hi = h;
}
// fp16 pair split with x256 prescale
__device__ __forceinline__ void split2h(float x0, float x1, uint32_t& hi, uint32_t& lo) {
    x0 *= 256.f; x1 *= 256.f;
    __half2 h = __floats2half2_rn(x0, x1);
    float f0 = __half2float(__low2half(h));
    float f1 = __half2float(__high2half(h));
    __half2 l = __floats2half2_rn(x0 - f0, x1 - f1);
    hi = *(uint32_t*)&h;
    lo = *(uint32_t*)&l;
}
__device__ __forceinline__ void mma16(float* d, const uint32_t* a, const uint32_t* b) {
    asm volatile("mma.sync.aligned.m16n8k16.row.col.f32.bf16.bf16.f32 "
                 "{%0,%1,%2,%3}, {%4,%5,%6,%7}, {%8,%9}, {%0,%1,%2,%3};"
                 : "+f"(d[0]), "+f"(d[1]), "+f"(d[2]), "+f"(d[3])
                 : "r"(a[0]), "r"(a[1]), "r"(a[2]), "r"(a[3]),
                   "r"(b[0]), "r"(b[1]));
}
__device__ __forceinline__ void mma16h(float* d, const uint32_t* a, const uint32_t* b) {
    asm volatile("mma.sync.aligned.m16n8k16.row.col.f32.f16.f16.f32 "
                 "{%0,%1,%2,%3}, {%4,%5,%6,%7}, {%8,%9}, {%0,%1,%2,%3};"
                 : "+f"(d[0]), "+f"(d[1]), "+f"(d[2]), "+f"(d[3])
                 : "r"(a[0]), "r"(a[1]), "r"(a[2]), "r"(a[3]),
                   "r"(b[0]), "r"(b[1]));
}
__device__ __forceinline__ float fex2(float z) {
    float r;
    asm("ex2.approx.f32 %0, %1;" : "=f"(r) : "f"(z));
    return r;
}

#define ACC_INIT() float acc[4][4][4];                                           \
    _Pragma("unroll") for (int a_ = 0; a_ < 4; a_++)                             \
    _Pragma("unroll") for (int b_ = 0; b_ < 4; b_++)                             \
    _Pragma("unroll") for (int c_ = 0; c_ < 4; c_++) acc[a_][b_][c_] = 0.f;

// ============================================================================
// prep: pre-split q_data, proj_w, lin_w into packed bf16 hi/lo pair arrays
// ============================================================================
__global__ void prep_kernel(const float* __restrict__ qd,
                            const float* __restrict__ pw,
                            const float* __restrict__ lw)
{
    int idx = blockIdx.x * 256 + threadIdx.x;
    if (idx < M_ALL * 128) {                       // q_data: [m][512]
        int m = idx >> 7, f = idx & 127;
        float4 v = *(const float4*)(qd + (size_t)m * 512 + f * 4);
        uint32_t h0, l0, h1, l1;
        split2(v.x, v.y, h0, l0); split2(v.z, v.w, h1, l1);
        *(uint2*)(g_qd + (size_t)m * 512 + 2 * f)       = make_uint2(h0, h1);
        *(uint2*)(g_qd + (size_t)m * 512 + 256 + 2 * f) = make_uint2(l0, l1);
        return;
    }
    idx -= M_ALL * 128;
    if (idx < 512 * 128) {                         // proj_w: [512][512]
        int n = idx >> 7, f = idx & 127;
        float4 v = *(const float4*)(pw + (size_t)n * 512 + f * 4);
        uint32_t h0, l0, h1, l1;
        split2(v.x, v.y, h0, l0); split2(v.z, v.w, h1, l1);
        *(uint2*)(g_pw + (size_t)n * 512 + 2 * f)       = make_uint2(h0, h1);
        *(uint2*)(g_pw + (size_t)n * 512 + 256 + 2 * f) = make_uint2(l0, l1);
        return;
    }
    idx -= 512 * 128;
    if (idx < 512 * 256) {                         // lin_w: [512][1024]
        int n = idx >> 8, f = idx & 255;
        float4 v = *(const float4*)(lw + (size_t)n * 1024 + f * 4);
        uint32_t h0, l0, h1, l1;
        split2(v.x, v.y, h0, l0); split2(v.z, v.w, h1, l1);
        *(uint2*)(g_lw + (size_t)n * 1024 + 2 * f)       = make_uint2(h0, h1);
        *(uint2*)(g_lw + (size_t)n * 1024 + 512 + 2 * f) = make_uint2(l0, l1);
    }
}

// ============================================================================
// QKV projections (split-in-loop; fp32 inputs). 128x64 tile, 4 warps 2x2.
// Q/K: fp16x3 core, epilogue writes packed fp16 pairs (x256) to g_q/g_k.
// V : bf16x3 core, epilogue writes fp32 to g_vs.
// ============================================================================
#define GPAD 36
#define BTPAD 68
#define G_SMEM_BT ((2*128*GPAD + 2*32*BTPAD)*4)   /* 54272 */

#define A_LOADR(buf, k0_) do {                                                    \
        int k0 = (k0_);                                                           \
        _Pragma("unroll")                                                         \
        for (int i = 0; i < 8; i++) {                                             \
            int id = tid + i * 128;                                               \
            int row = id >> 3, c4 = (id & 7) * 4;                                 \
            cp_async16(Abuf[buf] + row*GPAD + c4,                                 \
                       A1 + (size_t)(m0 + row)*Dm + k0 + c4);                     \
        }                                                                          \
    } while (0)
#define B_LOAD_BT(buf, k0_) do {                                                  \
        int k0 = (k0_);                                                           \
        _Pragma("unroll")                                                         \
        for (int i = 0; i < 4; i++) {                                             \
            int id = tid + i * 128;                                               \
            int kk = id >> 4, n4 = (id & 15) * 4;                                 \
            cp_async16(Bbuf[buf] + kk*BTPAD + n4,                                 \
                       Wh + (size_t)(k0 + kk)*64 + n4);                           \
        }                                                                          \
    } while (0)

// fp16x3, packed-pair epilogue
__device__ __forceinline__ void gemm_core_f16_bt_pk(
    const float* __restrict__ A1, const float* __restrict__ Wh,
    uint32_t* __restrict__ Cp, int m0, int n0, float* sm)
{
    float* Abuf[2] = { sm,              sm + 128*GPAD };
    float* Bbuf[2] = { sm + 2*128*GPAD, sm + 2*128*GPAD + 32*BTPAD };
    const int tid = threadIdx.x;
    const int wid = tid >> 5, lane = tid & 31;
    const int wm = wid & 1, wn = wid >> 1;
    const int lr = lane >> 2, lc = lane & 3;

    A_LOADR(0, 0); B_LOAD_BT(0, 0); CP_COMMIT();
    A_LOADR(1, 32); B_LOAD_BT(1, 32); CP_COMMIT();
    ACC_INIT()

    for (int c = 0; c < 16; c++) {
        if (c < 15) CP_WAIT1(); else CP_WAIT0();
        __syncthreads();
        const int buf = c & 1;
        const float* Ab = Abuf[buf] + wm * 64 * GPAD;
        const float* Bb = Bbuf[buf];
#pragma unroll
        for (int ks = 0; ks < 2; ks++) {
            const int kb = ks * 16 + 2 * lc;
            uint32_t bh[4][2], bl[4][2];
#pragma unroll
            for (int nt = 0; nt < 4; nt++) {
                int nl = wn*32 + nt*8 + lr;
                split2h(Bb[kb*BTPAD + nl],     Bb[(kb+1)*BTPAD + nl], bh[nt][0], bl[nt][0]);
                split2h(Bb[(kb+8)*BTPAD + nl], Bb[(kb+9)*BTPAD + nl], bh[nt][1], bl[nt][1]);
            }
#pragma unroll
            for (int mt = 0; mt < 4; mt++) {
                uint32_t ah[4], al[4];
                float2 a00 = *(const float2*)(Ab + (mt*16 + lr    )*GPAD + kb);
                float2 a10 = *(const float2*)(Ab + (mt*16 + lr + 8)*GPAD + kb);
                float2 a01 = *(const float2*)(Ab + (mt*16 + lr    )*GPAD + kb + 8);
                float2 a11 = *(const float2*)(Ab + (mt*16 + lr + 8)*GPAD + kb + 8);
                split2h(a00.x, a00.y, ah[0], al[0]);
                split2h(a10.x, a10.y, ah[1], al[1]);
                split2h(a01.x, a01.y, ah[2], al[2]);
                split2h(a11.x, a11.y, ah[3], al[3]);
#pragma unroll
                for (int nt = 0; nt < 4; nt++) {
                    mma16h(acc[mt][nt], ah, bh[nt]);
                    mma16h(acc[mt][nt], ah, bl[nt]);
                    mma16h(acc[mt][nt], al, bh[nt]);
                }
            }
        }
        __syncthreads();
        if (c + 2 < 16) { A_LOADR(buf, (c + 2) * 32); B_LOAD_BT(buf, (c + 2) * 32); CP_COMMIT(); }
    }
    // epilogue: unscale (2^-16), re-split as fp16 pairs (x256) and pack
#pragma unroll
    for (int mt = 0; mt < 4; mt++) {
#pragma unroll
        for (int nt = 0; nt < 4; nt++) {
            int row  = m0 + wm*64 + mt*16 + lr;
            int colp = wn*16 + nt*4 + lc;            // pair within head
            uint32_t hi, lo;
            split2h(acc[mt][nt][0]*UNSC, acc[mt][nt][1]*UNSC, hi, lo);
            Cp[(size_t)row*512 + n0 + colp]      = hi;
            Cp[(size_t)row*512 + n0 + 32 + colp] = lo;
            split2h(acc[mt][nt][2]*UNSC, acc[mt][nt][3]*UNSC, hi, lo);
            Cp[(size_t)(row+8)*512 + n0 + colp]      = hi;
            Cp[(size_t)(row+8)*512 + n0 + 32 + colp] = lo;
        }
    }
}

// bf16x3, fp32 epilogue (V projection)
__device__ __forceinline__ void gemm_core_bf_bt(
    const float* __restrict__ A1, const float* __restrict__ Wh,
    float* __restrict__ C, int m0, int n0, float* sm)
{
    float* Abuf[2] = { sm,              sm + 128*GPAD };
    float* Bbuf[2] = { sm + 2*128*GPAD, sm + 2*128*GPAD + 32*BTPAD };
    const int tid = threadIdx.x;
    const int wid = tid >> 5, lane = tid & 31;
    const int wm = wid & 1, wn = wid >> 1;
    const int lr = lane >> 2, lc = lane & 3;

    A_LOADR(0, 0); B_LOAD_BT(0, 0); CP_COMMIT();
    A_LOADR(1, 32); B_LOAD_BT(1, 32); CP_COMMIT();
    ACC_INIT()

    for (int c = 0; c < 16; c++) {
        if (c < 15) CP_WAIT1(); else CP_WAIT0();
        __syncthreads();
        const int buf = c & 1;
        const float* Ab = Abuf[buf] + wm * 64 * GPAD;
        const float* Bb = Bbuf[buf];
#pragma unroll
        for (int ks = 0; ks < 2; ks++) {
            const int kb = ks * 16 + 2 * lc;
            uint32_t bh[4][2], bl[4][2];
#pragma unroll
            for (int nt = 0; nt < 4; nt++) {
                int nl = wn*32 + nt*8 + lr;
                split2(Bb[kb*BTPAD + nl],     Bb[(kb+1)*BTPAD + nl], bh[nt][0], bl[nt][0]);
                split2(Bb[(kb+8)*BTPAD + nl], Bb[(kb+9)*BTPAD + nl], bh[nt][1], bl[nt][1]);
            }
#pragma unroll
            for (int mt = 0; mt < 4; mt++) {
                uint32_t ah[4], al[4];
                float2 a00 = *(const float2*)(Ab + (mt*16 + lr    )*GPAD + kb);
                float2 a10 = *(const float2*)(Ab + (mt*16 + lr + 8)*GPAD + kb);
                float2 a01 = *(const float2*)(Ab + (mt*16 + lr    )*GPAD + kb + 8);
                float2 a11 = *(const float2*)(Ab + (mt*16 + lr + 8)*GPAD + kb + 8);
                split2(a00.x, a00.y, ah[0], al[0]);
                split2(a10.x, a10.y, ah[1], al[1]);
                split2(a01.x, a01.y, ah[2], al[2]);
                split2(a11.x, a11.y, ah[3], al[3]);
#pragma unroll
                for (int nt = 0; nt < 4; nt++) {
                    mma16(acc[mt][nt], ah, bh[nt]);
                    mma16(acc[mt][nt], ah, bl[nt]);
                    mma16(acc[mt][nt], al, bh[nt]);
                }
            }
        }
        __syncthreads();
        if (c + 2 < 16) { A_LOADR(buf, (c + 2) * 32); B_LOAD_BT(buf, (c + 2) * 32); CP_COMMIT(); }
    }
#pragma unroll
    for (int mt = 0; mt < 4; mt++) {
#pragma unroll
        for (int nt = 0; nt < 4; nt++) {
            int row = m0 + wm*64 + mt*16 + lr;
            int col = n0 + wn*32 + nt*8 + 2*lc;
            *(float2*)(C + (size_t)row * Dm + col) =
                make_float2(acc[mt][nt][0], acc[mt][nt][1]);
            *(float2*)(C + (size_t)(row + 8) * Dm + col) =
                make_float2(acc[mt][nt][2], acc[mt][nt][3]);
        }
    }
}

__global__ __launch_bounds__(128, 3) void qkv_mma_bt(
    const float* __restrict__ qd, const float* __restrict__ kd, const float* __restrict__ vd,
    const float* __restrict__ wq, const float* __restrict__ wk, const float* __restrict__ wv)
{
    extern __shared__ float sm[];
    const int z = blockIdx.z;
    if (z == 2) {
        gemm_core_bf_bt(vd, wv + (size_t)blockIdx.x * Dm * 64, g_vs,
                        blockIdx.y * 128, blockIdx.x * 64, sm);
    } else {
        const float* A = (z == 0) ? qd : kd;
        const float* W = ((z == 0) ? wq : wk) + (size_t)blockIdx.x * Dm * 64;
        uint32_t* C = (z == 0) ? g_q : g_k;
        gemm_core_f16_bt_pk(A, W, C, blockIdx.y * 128, blockIdx.x * 64, sm);
    }
}

// ============================================================================
// Pre-split GEMM (proj / lin): pure LDS+HMMA inner loop, bf16x3.
// A rows: [m][512] u32 (hi 0..255, lo 256..511); for lin, k>=512 comes from A2.
// B rows: [n][ldb] u32 (hi 0..ldb/2-1, lo ldb/2..).
// C: fp32 (Cf) or packed bf16 pairs (Cp).
// ============================================================================
#define PKPAD 36
#define PK_SMEM ((2*128*PKPAD + 2*64*PKPAD)*4)   /* 55296 */
__global__ __launch_bounds__(128, 3) void gemm_pk(
    const uint32_t* __restrict__ A1, const uint32_t* __restrict__ A2,
    int K1h, int Kh, const uint32_t* __restrict__ Bm, int ldb,
    const float* __restrict__ bias, float* __restrict__ Cf, uint32_t* __restrict__ Cp)
{
    extern __shared__ uint32_t smu[];
    uint32_t* Abuf[2] = { smu,               smu + 128*PKPAD };
    uint32_t* Bbuf[2] = { smu + 2*128*PKPAD, smu + 2*128*PKPAD + 64*PKPAD };
    const int tid = threadIdx.x;
    const int wid = tid >> 5, lane = tid & 31;
    const int wm = wid & 1, wn = wid >> 1;
    const int lr = lane >> 2, lc = lane & 3;
    const int m0 = blockIdx.y * 128, n0 = blockIdx.x * 64;
    const int NC = Kh / 32;
    const int lob = ldb >> 1;

#define A_LOADP(buf, c_) do {                                                     \
        int k0 = (c_) * 32;                                                       \
        const uint32_t* Asrc; int p0;                                             \
        if (k0 < K1h) { Asrc = A1; p0 = k0 >> 1; }                                \
        else          { Asrc = A2; p0 = (k0 - K1h) >> 1; }                        \
        _Pragma("unroll")                                                         \
        for (int i = 0; i < 4; i++) {                                             \
            int id = tid + i * 128;                                               \
            int row = id >> 2, seg = (id & 3) * 4;                                \
            cp_async16(Abuf[buf] + row*PKPAD + seg,                               \
                       Asrc + (size_t)(m0 + row)*512 + p0 + seg);                 \
        }                                                                          \
        _Pragma("unroll")                                                         \
        for (int i = 0; i < 4; i++) {                                             \
            int id = tid + i * 128;                                               \
            int row = id >> 2, seg = (id & 3) * 4;                                \
            cp_async16(Abuf[buf] + row*PKPAD + 16 + seg,                          \
                       Asrc + (size_t)(m0 + row)*512 + 256 + p0 + seg);           \
        }                                                                          \
    } while (0)
#define B_LOADP(buf, c_) do {                                                     \
        int p0 = (c_) * 16;                                                       \
        _Pragma("unroll")                                                         \
        for (int i = 0; i < 2; i++) {                                             \
            int id = tid + i * 128;                                               \
            int row = id >> 2, seg = (id & 3) * 4;                                \
            cp_async16(Bbuf[buf] + row*PKPAD + seg,                               \
                       Bm + (size_t)(n0 + row)*ldb + p0 + seg);                   \
        }                                                                          \
        _Pragma("unroll")                                                         \
        for (int i = 0; i < 2; i++) {                                             \
            int id = tid + i * 128;                                               \
            int row = id >> 2, seg = (id & 3) * 4;                                \
            cp_async16(Bbuf[buf] + row*PKPAD + 16 + seg,                          \
                       Bm + (size_t)(n0 + row)*ldb + lob + p0 + seg);             \
        }                                                                          \
    } while (0)

    A_LOADP(0, 0); B_LOADP(0, 0); CP_COMMIT();
    A_LOADP(1, 1); B_LOADP(1, 1); CP_COMMIT();
    ACC_INIT()

    for (int c = 0; c < NC; c++) {
        if (c < NC - 1) CP_WAIT1(); else CP_WAIT0();
        __syncthreads();
        const int buf = c & 1;
        const uint32_t* Ab = Abuf[buf] + wm * 64 * PKPAD;
        const uint32_t* Bb = Bbuf[buf] + wn * 32 * PKPAD;
#pragma unroll
        for (int ks = 0; ks < 2; ks++) {
            const int cb = ks * 8 + lc;
            uint32_t bh[4][2], bl[4][2];
#pragma unroll
            for (int nt = 0; nt < 4; nt++) {
                int nl = nt*8 + lr;
                bh[nt][0] = Bb[nl*PKPAD + cb];
                bh[nt][1] = Bb[nl*PKPAD + cb + 4];
                bl[nt][0] = Bb[nl*PKPAD + 16 + cb];
                bl[nt][1] = Bb[nl*PKPAD + 16 + cb + 4];
            }
#pragma unroll
            for (int mt = 0; mt < 4; mt++) {
                uint32_t ah[4], al[4];
                ah[0] = Ab[(mt*16 + lr    )*PKPAD + cb];
                ah[1] = Ab[(mt*16 + lr + 8)*PKPAD + cb];
                ah[2] = Ab[(mt*16 + lr    )*PKPAD + cb + 4];
                ah[3] = Ab[(mt*16 + lr + 8)*PKPAD + cb + 4];
                al[0] = Ab[(mt*16 + lr    )*PKPAD + 16 + cb];
                al[1] = Ab[(mt*16 + lr + 8)*PKPAD + 16 + cb];
                al[2] = Ab[(mt*16 + lr    )*PKPAD + 16 + cb + 4];
                al[3] = Ab[(mt*16 + lr + 8)*PKPAD + 16 + cb + 4];
#pragma unroll
                for (int nt = 0; nt < 4; nt++) {
                    mma16(acc[mt][nt], ah, bh[nt]);
                    mma16(acc[mt][nt], ah, bl[nt]);
                    mma16(acc[mt][nt], al, bh[nt]);
                }
            }
        }
        __syncthreads();
        if (c + 2 < NC) { A_LOADP(buf, c + 2); B_LOADP(buf, c + 2); CP_COMMIT(); }
    }

#pragma unroll
    for (int mt = 0; mt < 4; mt++) {
#pragma unroll
        for (int nt = 0; nt < 4; nt++) {
            int row = m0 + wm*64 + mt*16 + lr;
            int col = n0 + wn*32 + nt*8 + 2*lc;
            float bx = bias[col], by = bias[col + 1];
            if (Cp) {
                int pair = col >> 1;
                uint32_t hi, lo;
                split2(acc[mt][nt][0] + bx, acc[mt][nt][1] + by, hi, lo);
                Cp[(size_t)row*512 + pair] = hi;
                Cp[(size_t)row*512 + 256 + pair] = lo;
                split2(acc[mt][nt][2] + bx, acc[mt][nt][3] + by, hi, lo);
                Cp[(size_t)(row+8)*512 + pair] = hi;
                Cp[(size_t)(row+8)*512 + 256 + pair] = lo;
            } else {
                *(float2*)(Cf + (size_t)row * Dm + col) =
                    make_float2(acc[mt][nt][0] + bx, acc[mt][nt][1] + by);
                *(float2*)(Cf + (size_t)(row + 8) * Dm + col) =
                    make_float2(acc[mt][nt][2] + bx, acc[mt][nt][3] + by);
            }
        }
    }
#undef A_LOADP
#undef B_LOADP
}

// ============================================================================
// QK^T (pre-split fp16 pairs, pure LDS+HMMA) + softmax stats + dense attn fill.
// CTA = (h, b, 128 q rows); 16 K-tiles of 64 rows.
// smem rows: 64 u32 (32 hi | 32 lo) + pad 4 -> stride 68.
// ============================================================================
#define APADU 68
#define S_SMEM ((128*APADU + 2*64*APADU)*4 + 256*4*3)  /* 72704 */
__global__ __launch_bounds__(128, 3) void attn_stats_mma(float* __restrict__ attn)
{
    extern __shared__ uint32_t smu[];
    uint32_t* Qs = smu;
    uint32_t* Kbuf[2] = { smu + 128*APADU, smu + 128*APADU + 64*APADU };
    float* redm = (float*)(smu + 128*APADU + 2*64*APADU);
    float* reds = redm + 256;
    int*   redi = (int*)(reds + 256);

    const int tid = threadIdx.x;
    const int h = blockIdx.z, b = blockIdx.y, q0 = blockIdx.x * 128;
    const int wid = tid >> 5, lane = tid & 31;
    const int wm = wid & 1, wn = wid >> 1;
    const int lr = lane >> 2, lc = lane & 3;

    const uint32_t* Qg = g_q + ((size_t)(b * Ls + q0)) * 512 + h * 64;
    const uint32_t* Kg = g_k + ((size_t)(b * Ls)) * 512 + h * 64;
    const size_t rowbase = (size_t)(h * Bn + b) * Ls + q0;

#pragma unroll
    for (int i = 0; i < 16; i++) {
        int id = tid + i * 128;
        int row = id >> 4, seg = (id & 15) * 4;
        cp_async16(Qs + row*APADU + seg, Qg + (size_t)row * 512 + seg);
    }
    CP_COMMIT();

#define K_LOAD(buf, t_) do {                                                    \
        _Pragma("unroll")                                                       \
        for (int i = 0; i < 8; i++) {                                           \
            int id = tid + i * 128;                                             \
            int row = id >> 4, seg = (id & 15) * 4;                             \
            cp_async16(Kbuf[buf] + row*APADU + seg,                             \
                       Kg + (size_t)((t_)*64 + row) * 512 + seg);               \
        }                                                                       \
    } while (0)

    K_LOAD(0, 0); CP_COMMIT();
    K_LOAD(1, 1); CP_COMMIT();

    float rm[8], rs[8];
    int ridx[8];
#pragma unroll
    for (int i = 0; i < 8; i++) { rm[i] = -1e30f; rs[i] = 0.f; ridx[i] = 0; }

    for (int t = 0; t < 16; t++) {
        if (t < 15) CP_WAIT1(); else CP_WAIT0();
        __syncthreads();
        const int buf = t & 1;
        const uint32_t* Ab = Qs + wm * 64 * APADU;
        const uint32_t* Bb = Kbuf[buf] + wn * 32 * APADU;

        ACC_INIT()

#pragma unroll
        for (int ks = 0; ks < 4; ks++) {            // dk=64 halves = 32 pairs
            const int cb = ks * 8 + lc;
            uint32_t bh[4][2], bl[4][2];
#pragma unroll
            for (int nt = 0; nt < 4; nt++) {
                int nl = nt*8 + lr;
                bh[nt][0] = Bb[nl*APADU + cb];
                bh[nt][1] = Bb[nl*APADU + cb + 4];
                bl[nt][0] = Bb[nl*APADU + 32 + cb];
                bl[nt][1] = Bb[nl*APADU + 32 + cb + 4];
            }
#pragma unroll
            for (int mt = 0; mt < 4; mt++) {
                uint32_t ah[4], al[4];
                ah[0] = Ab[(mt*16 + lr    )*APADU + cb];
                ah[1] = Ab[(mt*16 + lr + 8)*APADU + cb];
                ah[2] = Ab[(mt*16 + lr    )*APADU + cb + 4];
                ah[3] = Ab[(mt*16 + lr + 8)*APADU + cb + 4];
                al[0] = Ab[(mt*16 + lr    )*APADU + 32 + cb];
                al[1] = Ab[(mt*16 + lr + 8)*APADU + 32 + cb];
                al[2] = Ab[(mt*16 + lr    )*APADU + 32 + cb + 4];
                al[3] = Ab[(mt*16 + lr + 8)*APADU + 32 + cb + 4];
#pragma unroll
                for (int nt = 0; nt < 4; nt++) {
                    mma16h(acc[mt][nt], ah, bh[nt]);
                    mma16h(acc[mt][nt], ah, bl[nt]);
                    mma16h(acc[mt][nt], al, bh[nt]);
                }
            }
        }

        // streaming zero-fill of this CTA's attn slice, s-range [t*64, t*64+64)
        {
            float4 z4 = make_float4(0.f, 0.f, 0.f, 0.f);
#pragma unroll
            for (int i = 0; i < 16; i++) {
                int id = tid + i * 128;
                int r = id >> 4, f4 = id & 15;
                __stcs((float4*)(attn + (rowbase + r) * Ls + t * 64 + f4 * 4), z4);
            }
        }

        // fold tile into per-thread stats
        const int sbase = t * 64 + wn * 32 + 2 * lc;
#pragma unroll
        for (int mt = 0; mt < 4; mt++) {
#pragma unroll
            for (int half = 0; half < 2; half++) {
                const int r8 = mt * 2 + half;
                float m = rm[r8], s_ = rs[r8];
                int id_ = ridx[r8];
#pragma unroll
                for (int nt = 0; nt < 4; nt++) {
#pragma unroll
                    for (int j = 0; j < 2; j++) {
                        float v = acc[mt][nt][half*2 + j];
                        if (v > m) { m = v; id_ = sbase + nt*8 + j; }
                        s_ += fex2(v * CCH);
                    }
                }
                rm[r8] = m; rs[r8] = s_; ridx[r8] = id_;
            }
        }
        __syncthreads();
        if (t + 2 < 16) { K_LOAD(buf, t + 2); CP_COMMIT(); }
    }

    // quad reduce over lc
#pragma unroll
    for (int r8 = 0; r8 < 8; r8++) {
        float m = rm[r8], s_ = rs[r8];
        int id_ = ridx[r8];
#pragma unroll
        for (int off = 1; off <= 2; off <<= 1) {
            float om = __shfl_xor_sync(0xffffffffu, m, off);
            float os = __shfl_xor_sync(0xffffffffu, s_, off);
            int   oi = __shfl_xor_sync(0xffffffffu, id_, off);
            s_ += os;
            if (om > m) { m = om; id_ = oi; }
        }
        if (lc == 0) {
            int rowl = wm*64 + (r8 >> 1)*16 + (r8 & 1)*8 + lr;
            redm[rowl*2 + wn] = m;
            reds[rowl*2 + wn] = s_;
            redi[rowl*2 + wn] = id_;
        }
    }
    __syncthreads();

    {
        float m = redm[tid*2], s_ = reds[tid*2];
        int id_ = redi[tid*2];
        float om = redm[tid*2 + 1];
        s_ += reds[tid*2 + 1];
        if (om > m) { m = om; id_ = redi[tid*2 + 1]; }
        float p = fex2(m * CCH) / s_;
        int row = (int)(rowbase) + tid;
        g_p[row] = p;
        g_amax[row] = id_;
        attn[(rowbase + tid) * Ls + id_] = p;
    }
#undef K_LOAD
}

// ============================================================================
// attn @ V gather -> packed bf16 headout pairs
// ============================================================================
__global__ void gather_kernel()
{
    int idx4 = blockIdx.x * blockDim.x + threadIdx.x;   // over M_ALL*Dm/4
    if (idx4 >= M_ALL * Dm / 4) return;
    int e4 = idx4 & 15;
    int h  = (idx4 >> 4) & 7;
    int m  = idx4 >> 7;
    int b  = m >> 10;
    int q  = m & 1023;
    int row = (h * Bn + b) * Ls + q;
    float p = g_p[row];
    int   s = g_amax[row];
    float4 v = *(const float4*)(g_vs + ((size_t)(b * Ls + s)) * Dm + h * 64 + e4 * 4);
    uint32_t h0, l0, h1, l1;
    split2(v.x * p, v.y * p, h0, l0);
    split2(v.z * p, v.w * p, h1, l1);
    int pairbase = h * 32 + e4 * 2;
    *(uint2*)(g_ho + (size_t)m * 512 + pairbase)       = make_uint2(h0, h1);
    *(uint2*)(g_ho + (size_t)m * 512 + 256 + pairbase) = make_uint2(l0, l1);
}

// ============================================================================
extern "C" void kernel_launch(void* const* d_in, const int* in_sizes, int n_in,
                              void* d_out, int out_size)
{
    const float* q_data = (const float*)d_in[0];
    const float* k_data = (const float*)d_in[1];
    const float* v_data = (const float*)d_in[2];
    const float* w_qs   = (const float*)d_in[3];
    const float* w_ks   = (const float*)d_in[4];
    const float* w_vs   = (const float*)d_in[5];
    const float* proj_w = (const float*)d_in[6];
    const float* proj_b = (const float*)d_in[7];
    const float* lin_w  = (const float*)d_in[8];
    const float* lin_b  = (const float*)d_in[9];

    float* out  = (float*)d_out;                    // [B, L, D]
    float* attn = out + OUT_ELEMS;                  // [H*B, L, L]

    uint32_t *p_ho, *p_po, *p_qd, *p_pw, *p_lw;
    cudaGetSymbolAddress((void**)&p_ho, g_ho);
    cudaGetSymbolAddress((void**)&p_po, g_po);
    cudaGetSymbolAddress((void**)&p_qd, g_qd);
    cudaGetSymbolAddress((void**)&p_pw, g_pw);
    cudaGetSymbolAddress((void**)&p_lw, g_lw);

    cudaFuncSetAttribute(qkv_mma_bt, cudaFuncAttributeMaxDynamicSharedMemorySize, G_SMEM_BT);
    cudaFuncSetAttribute(gemm_pk,    cudaFuncAttributeMaxDynamicSharedMemorySize, PK_SMEM);
    cudaFuncSetAttribute(attn_stats_mma, cudaFuncAttributeMaxDynamicSharedMemorySize, S_SMEM);

    // 0) pre-split q_data / proj_w / lin_w into packed bf16 pair arrays
    prep_kernel<<<(M_ALL*128 + 512*128 + 512*256 + 255) / 256, 256>>>(q_data, proj_w, lin_w);

    // 1) Q/K/V projections (Q,K fp16x3 -> packed fp16; V bf16x3 -> fp32)
    qkv_mma_bt<<<dim3(8, 128, 3), 128, G_SMEM_BT>>>(q_data, k_data, v_data,
                                                    w_qs, w_ks, w_vs);

    // 2) QK^T + softmax stats + dense attn fill (pre-split, pure LDS+HMMA)
    attn_stats_mma<<<dim3(8, 16, 8), 128, S_SMEM>>>(attn);

    // 3) attn @ V gather -> packed bf16 headout
    gather_kernel<<<(M_ALL * Dm / 4 + 255) / 256, 256>>>();

    // 4) output projection (pre-split) -> packed bf16 projout
    gemm_pk<<<dim3(8, 128), 128, PK_SMEM>>>(p_ho, p_ho, 512, 512, p_pw, 512,
                                            proj_b, nullptr, p_po);

    // 5) final linear (pre-split): out = [q_data | projout] @ lin_w^T + lin_b
    gemm_pk<<<dim3(8, 128), 128, PK_SMEM>>>(p_qd, p_po, 512, 1024, p_lw, 1024,
                                            lin_b, out, nullptr);
}

// round 11
// speedup vs baseline: 1.5007x; 1.0867x over previous
#include <cuda_runtime.h>
#include <cuda_fp16.h>
#include <cstdint>

#define Hh 8
#define Bn 16
#define Ls 1024
#define Dm 512
#define M_ALL (Bn*Ls)              /* 16384 */
#define OUT_ELEMS (Bn*Ls*Dm)       /* 8388608 */
#define NROWS (Hh*Bn*Ls)           /* 131072 */
#define CCH  9.728829e-7f          /* (1/sqrt(512))*log2(e)/65536 */
#define UNSC 1.52587890625e-5f     /* 2^-16 */

// ---------------- static device scratch (packed-pair u32 = 2 b16, consec k) --
__device__ uint32_t g_q  [M_ALL*512];   // Q proj, fp16 x256; head h: hi [h*64..+32), lo [+32..+64)
__device__ uint32_t g_k  [M_ALL*512];
__device__ float    g_vs [M_ALL*Dm];    // V proj fp32
__device__ uint32_t g_ho [M_ALL*512];   // headout bf16: hi [0,256), lo [256,512)
__device__ uint32_t g_po [M_ALL*512];   // projout bf16
__device__ uint32_t g_qd [M_ALL*512];   // q_data bf16 (lin A1)
__device__ uint32_t g_qdh[M_ALL*512];   // q_data fp16 x256 (Q proj A)
__device__ uint32_t g_kdh[M_ALL*512];   // k_data fp16 x256
__device__ uint32_t g_vdb[M_ALL*512];   // v_data bf16
__device__ uint32_t g_wqt[512*512];     // wq^T fp16 x256: [n=h*64+e][hi 256 | lo 256]
__device__ uint32_t g_wkt[512*512];
__device__ uint32_t g_wvt[512*512];     // bf16
__device__ uint32_t g_pw [512*512];     // proj_w bf16 [n][hi 256|lo 256]
__device__ uint32_t g_lw [512*1024];    // lin_w bf16 [n][hi 512|lo 512]
__device__ float g_p[NROWS];
__device__ int   g_amax[NROWS];

// ---------------- helpers ----------------
__device__ __forceinline__ uint32_t smem_u32(const void* p) {
    uint32_t a;
    asm("{ .reg .u64 t; cvta.to.shared.u64 t, %1; cvt.u32.u64 %0, t; }" : "=r"(a) : "l"(p));
    return a;
}
__device__ __forceinline__ void cp_async16(void* sdst, const void* gsrc) {
    uint32_t s = smem_u32(sdst);
    asm volatile("cp.async.ca.shared.global [%0], [%1], 16;" :: "r"(s), "l"(gsrc));
}
#define CP_COMMIT() asm volatile("cp.async.commit_group;" ::: "memory")
#define CP_WAIT1()  asm volatile("cp.async.wait_group 1;" ::: "memory")
#define CP_WAIT0()  asm volatile("cp.async.wait_group 0;" ::: "memory")

__device__ __forceinline__ void split2(float x0, float x1, uint32_t& hi, uint32_t& lo) {
    uint32_t h;
    asm("cvt.rn.bf16x2.f32 %0, %1, %2;" : "=r"(h) : "f"(x1), "f"(x0));
    float h0 = __uint_as_float(h << 16);
    float h1 = __uint_as_float(h & 0xffff0000u);
    float r0 = x0 - h0, r1 = x1 - h1;
    asm("cvt.rn.bf16x2.f32 %0, %1, %2;" : "=r"(lo) : "f"(r1), "f"(r0));
    hi = h;
}
__device__ __forceinline__ void split2h(float x0, float x1, uint32_t& hi, uint32_t& lo) {
    x0 *= 256.f; x1 *= 256.f;
    __half2 h = __floats2half2_rn(x0, x1);
    float f0 = __half2float(__low2half(h));
    float f1 = __half2float(__high2half(h));
    __half2 l = __floats2half2_rn(x0 - f0, x1 - f1);
    hi = *(uint32_t*)&h;
    lo = *(uint32_t*)&l;
}
__device__ __forceinline__ void mma16(float* d, const uint32_t* a, const uint32_t* b) {
    asm volatile("mma.sync.aligned.m16n8k16.row.col.f32.bf16.bf16.f32 "
                 "{%0,%1,%2,%3}, {%4,%5,%6,%7}, {%8,%9}, {%0,%1,%2,%3};"
                 : "+f"(d[0]), "+f"(d[1]), "+f"(d[2]), "+f"(d[3])
                 : "r"(a[0]), "r"(a[1]), "r"(a[2]), "r"(a[3]),
                   "r"(b[0]), "r"(b[1]));
}
__device__ __forceinline__ void mma16h(float* d, const uint32_t* a, const uint32_t* b) {
    asm volatile("mma.sync.aligned.m16n8k16.row.col.f32.f16.f16.f32 "
                 "{%0,%1,%2,%3}, {%4,%5,%6,%7}, {%8,%9}, {%0,%1,%2,%3};"
                 : "+f"(d[0]), "+f"(d[1]), "+f"(d[2]), "+f"(d[3])
                 : "r"(a[0]), "r"(a[1]), "r"(a[2]), "r"(a[3]),
                   "r"(b[0]), "r"(b[1]));
}
__device__ __forceinline__ void ldsm4(uint32_t* r, uint32_t a) {
    asm volatile("ldmatrix.sync.aligned.m8n8.x4.shared.b16 {%0,%1,%2,%3}, [%4];"
                 : "=r"(r[0]), "=r"(r[1]), "=r"(r[2]), "=r"(r[3]) : "r"(a));
}
__device__ __forceinline__ float fex2(float z) {
    float r;
    asm("ex2.approx.f32 %0, %1;" : "=f"(r) : "f"(z));
    return r;
}

#define ACC_INIT() float acc[4][4][4];                                           \
    _Pragma("unroll") for (int a_ = 0; a_ < 4; a_++)                             \
    _Pragma("unroll") for (int b_ = 0; b_ < 4; b_++)                             \
    _Pragma("unroll") for (int c_ = 0; c_ < 4; c_++) acc[a_][b_][c_] = 0.f;

// ============================================================================
// prep: split activations + weights into packed-pair arrays
// ============================================================================
__global__ void prep_act(const float* __restrict__ qd, const float* __restrict__ kd,
                         const float* __restrict__ vd)
{
    int idx = blockIdx.x * 256 + threadIdx.x;        // over 3*M_ALL*128
    int which = idx / (M_ALL * 128);
    int r = idx - which * (M_ALL * 128);
    int m = r >> 7, f = r & 127;
    uint32_t h0, l0, h1, l1;
    if (which == 0) {
        float4 v = *(const float4*)(qd + (size_t)m * 512 + f * 4);
        split2h(v.x, v.y, h0, l0); split2h(v.z, v.w, h1, l1);
        *(uint2*)(g_qdh + (size_t)m * 512 + 2 * f)       = make_uint2(h0, h1);
        *(uint2*)(g_qdh + (size_t)m * 512 + 256 + 2 * f) = make_uint2(l0, l1);
        split2(v.x, v.y, h0, l0); split2(v.z, v.w, h1, l1);
        *(uint2*)(g_qd + (size_t)m * 512 + 2 * f)       = make_uint2(h0, h1);
        *(uint2*)(g_qd + (size_t)m * 512 + 256 + 2 * f) = make_uint2(l0, l1);
    } else if (which == 1) {
        float4 v = *(const float4*)(kd + (size_t)m * 512 + f * 4);
        split2h(v.x, v.y, h0, l0); split2h(v.z, v.w, h1, l1);
        *(uint2*)(g_kdh + (size_t)m * 512 + 2 * f)       = make_uint2(h0, h1);
        *(uint2*)(g_kdh + (size_t)m * 512 + 256 + 2 * f) = make_uint2(l0, l1);
    } else {
        float4 v = *(const float4*)(vd + (size_t)m * 512 + f * 4);
        split2(v.x, v.y, h0, l0); split2(v.z, v.w, h1, l1);
        *(uint2*)(g_vdb + (size_t)m * 512 + 2 * f)       = make_uint2(h0, h1);
        *(uint2*)(g_vdb + (size_t)m * 512 + 256 + 2 * f) = make_uint2(l0, l1);
    }
}

__global__ void prep_w(const float* __restrict__ wq, const float* __restrict__ wk,
                       const float* __restrict__ wv, const float* __restrict__ pw,
                       const float* __restrict__ lw)
{
    int idx = blockIdx.x * 256 + threadIdx.x;
    if (idx < 3 * 8 * 256 * 64) {                    // qkv weights, transposed split
        int e = idx & 63;
        int p = (idx >> 6) & 255;
        int h = (idx >> 14) & 7;
        int z = idx >> 17;
        const float* W = ((z == 0) ? wq : (z == 1) ? wk : wv) + (size_t)h * 512 * 64;
        float x0 = W[(size_t)(2 * p) * 64 + e];
        float x1 = W[(size_t)(2 * p + 1) * 64 + e];
        int n = h * 64 + e;
        uint32_t hi, lo;
        if (z == 2) {
            split2(x0, x1, hi, lo);
            g_wvt[(size_t)n * 512 + p] = hi; g_wvt[(size_t)n * 512 + 256 + p] = lo;
        } else {
            split2h(x0, x1, hi, lo);
            uint32_t* dst = (z == 0) ? g_wqt : g_wkt;
            dst[(size_t)n * 512 + p] = hi; dst[(size_t)n * 512 + 256 + p] = lo;
        }
        return;
    }
    idx -= 3 * 8 * 256 * 64;
    uint32_t h0, l0, h1, l1;
    if (idx < 512 * 128) {                           // proj_w
        int n = idx >> 7, f = idx & 127;
        float4 v = *(const float4*)(pw + (size_t)n * 512 + f * 4);
        split2(v.x, v.y, h0, l0); split2(v.z, v.w, h1, l1);
        *(uint2*)(g_pw + (size_t)n * 512 + 2 * f)       = make_uint2(h0, h1);
        *(uint2*)(g_pw + (size_t)n * 512 + 256 + 2 * f) = make_uint2(l0, l1);
        return;
    }
    idx -= 512 * 128;
    if (idx < 512 * 256) {                           // lin_w
        int n = idx >> 8, f = idx & 255;
        float4 v = *(const float4*)(lw + (size_t)n * 1024 + f * 4);
        split2(v.x, v.y, h0, l0); split2(v.z, v.w, h1, l1);
        *(uint2*)(g_lw + (size_t)n * 1024 + 2 * f)       = make_uint2(h0, h1);
        *(uint2*)(g_lw + (size_t)n * 1024 + 512 + 2 * f) = make_uint2(l0, l1);
    }
}

// ============================================================================
// Unified pre-split GEMM core: pure ldmatrix+HMMA. 128x64 CTA tile, 4 warps
// 2(M)x2(N), warp tile 64x32, chunks of 16 pairs (k=32), cp.async dbuf.
// A rows: [m][512] u32 (hi 0..255 | lo 256..511). B rows: [n][ldb] (lo at ldb/2).
// EPI: 0 = packed fp16 x256 (Q/K out), 1 = fp32 (V out),
//      2 = packed bf16 + bias (proj out), 3 = fp32 + bias (final out)
// ============================================================================
#define PKPAD 36
#define PK_SMEM ((2*128*PKPAD + 2*64*PKPAD)*4)   /* 55296 */

template<bool FP16, int EPI>
__device__ __forceinline__ void pk_core(
    const uint32_t* __restrict__ A1, const uint32_t* __restrict__ A2, int K1p, int Kp,
    const uint32_t* __restrict__ Bm, int ldb,
    const float* __restrict__ bias, float* __restrict__ Cf, uint32_t* __restrict__ Cp,
    int m0, int n0, uint32_t* smu)
{
    uint32_t* Abuf[2] = { smu,               smu + 128*PKPAD };
    uint32_t* Bbuf[2] = { smu + 2*128*PKPAD, smu + 2*128*PKPAD + 64*PKPAD };
    const int tid = threadIdx.x;
    const int wid = tid >> 5, lane = tid & 31;
    const int wm = wid & 1, wn = wid >> 1;
    const int lr = lane >> 2, lc = lane & 3;
    const int NC = Kp / 16;
    const int lob = ldb >> 1;

    // lane-fixed ldmatrix offsets (u32 units)
    const int a_off = ((lane&7) + ((lane>>3)&1)*8)*PKPAD + (lane>>4)*4;
    const int b_off = (lane&7)*PKPAD + ((lane>>3)&1)*4 + (lane>>4)*16;
    uint32_t a_sh[2], b_sh[2];
    a_sh[0] = smem_u32(Abuf[0]) + (wm*64*PKPAD + a_off)*4;
    a_sh[1] = smem_u32(Abuf[1]) + (wm*64*PKPAD + a_off)*4;
    b_sh[0] = smem_u32(Bbuf[0]) + (wn*32*PKPAD + b_off)*4;
    b_sh[1] = smem_u32(Bbuf[1]) + (wn*32*PKPAD + b_off)*4;

#define A_LOADP(buf, c_) do {                                                     \
        int p0_; const uint32_t* Asrc;                                            \
        if ((c_)*16 < K1p) { Asrc = A1; p0_ = (c_)*16; }                          \
        else               { Asrc = A2; p0_ = (c_)*16 - K1p; }                    \
        _Pragma("unroll")                                                         \
        for (int i = 0; i < 4; i++) {                                             \
            int id = tid + i * 128;                                               \
            int row = id >> 2, seg = (id & 3) * 4;                                \
            cp_async16(Abuf[buf] + row*PKPAD + seg,                               \
                       Asrc + (size_t)(m0 + row)*512 + p0_ + seg);                \
        }                                                                          \
        _Pragma("unroll")                                                         \
        for (int i = 0; i < 4; i++) {                                             \
            int id = tid + i * 128;                                               \
            int row = id >> 2, seg = (id & 3) * 4;                                \
            cp_async16(Abuf[buf] + row*PKPAD + 16 + seg,                          \
                       Asrc + (size_t)(m0 + row)*512 + 256 + p0_ + seg);          \
        }                                                                          \
    } while (0)
#define B_LOADP(buf, c_) do {                                                     \
        int p0_ = (c_) * 16;                                                      \
        _Pragma("unroll")                                                         \
        for (int i = 0; i < 2; i++) {                                             \
            int id = tid + i * 128;                                               \
            int row = id >> 2, seg = (id & 3) * 4;                                \
            cp_async16(Bbuf[buf] + row*PKPAD + seg,                               \
                       Bm + (size_t)(n0 + row)*ldb + p0_ + seg);                  \
        }                                                                          \
        _Pragma("unroll")                                                         \
        for (int i = 0; i < 2; i++) {                                             \
            int id = tid + i * 128;                                               \
            int row = id >> 2, seg = (id & 3) * 4;                                \
            cp_async16(Bbuf[buf] + row*PKPAD + 16 + seg,                          \
                       Bm + (size_t)(n0 + row)*ldb + lob + p0_ + seg);            \
        }                                                                          \
    } while (0)

    A_LOADP(0, 0); B_LOADP(0, 0); CP_COMMIT();
    A_LOADP(1, 1); B_LOADP(1, 1); CP_COMMIT();
    ACC_INIT()

    for (int c = 0; c < NC; c++) {
        if (c < NC - 1) CP_WAIT1(); else CP_WAIT0();
        __syncthreads();
        const int buf = c & 1;
#pragma unroll
        for (int ks = 0; ks < 2; ks++) {
            uint32_t bfr[4][4];
#pragma unroll
            for (int nt = 0; nt < 4; nt++)
                ldsm4(bfr[nt], b_sh[buf] + (nt*8*PKPAD + ks*8)*4);
#pragma unroll
            for (int mt = 0; mt < 4; mt++) {
                uint32_t ah[4], al[4];
                uint32_t aa = a_sh[buf] + (mt*16*PKPAD + ks*8)*4;
                ldsm4(ah, aa);
                ldsm4(al, aa + 64);
#pragma unroll
                for (int nt = 0; nt < 4; nt++) {
                    if (FP16) {
                        mma16h(acc[mt][nt], ah, bfr[nt]);
                        mma16h(acc[mt][nt], ah, bfr[nt] + 2);
                        mma16h(acc[mt][nt], al, bfr[nt]);
                    } else {
                        mma16(acc[mt][nt], ah, bfr[nt]);
                        mma16(acc[mt][nt], ah, bfr[nt] + 2);
                        mma16(acc[mt][nt], al, bfr[nt]);
                    }
                }
            }
        }
        __syncthreads();
        if (c + 2 < NC) { A_LOADP(buf, c + 2); B_LOADP(buf, c + 2); CP_COMMIT(); }
    }

#pragma unroll
    for (int mt = 0; mt < 4; mt++) {
#pragma unroll
        for (int nt = 0; nt < 4; nt++) {
            int row = m0 + wm*64 + mt*16 + lr;
            if (EPI == 0) {
                int colp = wn*16 + nt*4 + lc;
                uint32_t hi, lo;
                split2h(acc[mt][nt][0]*UNSC, acc[mt][nt][1]*UNSC, hi, lo);
                Cp[(size_t)row*512 + n0 + colp]      = hi;
                Cp[(size_t)row*512 + n0 + 32 + colp] = lo;
                split2h(acc[mt][nt][2]*UNSC, acc[mt][nt][3]*UNSC, hi, lo);
                Cp[(size_t)(row+8)*512 + n0 + colp]      = hi;
                Cp[(size_t)(row+8)*512 + n0 + 32 + colp] = lo;
            } else if (EPI == 1) {
                int col = n0 + wn*32 + nt*8 + 2*lc;
                *(float2*)(Cf + (size_t)row * Dm + col) =
                    make_float2(acc[mt][nt][0], acc[mt][nt][1]);
                *(float2*)(Cf + (size_t)(row + 8) * Dm + col) =
                    make_float2(acc[mt][nt][2], acc[mt][nt][3]);
            } else if (EPI == 2) {
                int col = n0 + wn*32 + nt*8 + 2*lc;
                float bx = bias[col], by = bias[col + 1];
                int pair = col >> 1;
                uint32_t hi, lo;
                split2(acc[mt][nt][0] + bx, acc[mt][nt][1] + by, hi, lo);
                Cp[(size_t)row*512 + pair] = hi;
                Cp[(size_t)row*512 + 256 + pair] = lo;
                split2(acc[mt][nt][2] + bx, acc[mt][nt][3] + by, hi, lo);
                Cp[(size_t)(row+8)*512 + pair] = hi;
                Cp[(size_t)(row+8)*512 + 256 + pair] = lo;
            } else {
                int col = n0 + wn*32 + nt*8 + 2*lc;
                float bx = bias[col], by = bias[col + 1];
                *(float2*)(Cf + (size_t)row * Dm + col) =
                    make_float2(acc[mt][nt][0] + bx, acc[mt][nt][1] + by);
                *(float2*)(Cf + (size_t)(row + 8) * Dm + col) =
                    make_float2(acc[mt][nt][2] + bx, acc[mt][nt][3] + by);
            }
        }
    }
#undef A_LOADP
#undef B_LOADP
}

__global__ __launch_bounds__(128, 3) void qkv_pk()
{
    extern __shared__ uint32_t smu[];
    const int z = blockIdx.z;
    const int m0 = blockIdx.y * 128, n0 = blockIdx.x * 64;
    if (z == 0)
        pk_core<true, 0>(g_qdh, g_qdh, 256, 256, g_wqt, 512, nullptr, nullptr, g_q, m0, n0, smu);
    else if (z == 1)
        pk_core<true, 0>(g_kdh, g_kdh, 256, 256, g_wkt, 512, nullptr, nullptr, g_k, m0, n0, smu);
    else
        pk_core<false, 1>(g_vdb, g_vdb, 256, 256, g_wvt, 512, nullptr, g_vs, nullptr, m0, n0, smu);
}

__global__ __launch_bounds__(128, 3) void proj_pk(const float* __restrict__ bias)
{
    extern __shared__ uint32_t smu[];
    pk_core<false, 2>(g_ho, g_ho, 256, 256, g_pw, 512, bias, nullptr, g_po,
                      blockIdx.y * 128, blockIdx.x * 64, smu);
}

__global__ __launch_bounds__(128, 3) void lin_pk(const float* __restrict__ bias,
                                                 float* __restrict__ out)
{
    extern __shared__ uint32_t smu[];
    pk_core<false, 3>(g_qd, g_po, 256, 512, g_lw, 1024, bias, out, nullptr,
                      blockIdx.y * 128, blockIdx.x * 64, smu);
}

// ============================================================================
// QK^T (ldmatrix + fp16 HMMA) + softmax stats + dense attn fill, fused.
// CTA = (h, b, 128 q rows); 16 K-tiles of 64 rows. Staged rows: 64 u32
// (hi 32 | lo 32), stride 68 (conflict-free for ldmatrix phases).
// ============================================================================
#define APADU 68
#define S_SMEM ((128*APADU + 2*64*APADU)*4 + 256*4*3)  /* 72704 */
__global__ __launch_bounds__(128, 3) void attn_stats_mma(float* __restrict__ attn)
{
    extern __shared__ uint32_t smu[];
    uint32_t* Qs = smu;
    uint32_t* Kbuf[2] = { smu + 128*APADU, smu + 128*APADU + 64*APADU };
    float* redm = (float*)(smu + 128*APADU + 2*64*APADU);
    float* reds = redm + 256;
    int*   redi = (int*)(reds + 256);

    const int tid = threadIdx.x;
    const int h = blockIdx.z, b = blockIdx.y, q0 = blockIdx.x * 128;
    const int wid = tid >> 5, lane = tid & 31;
    const int wm = wid & 1, wn = wid >> 1;
    const int lr = lane >> 2, lc = lane & 3;

    const uint32_t* Qg = g_q + ((size_t)(b * Ls + q0)) * 512 + h * 64;
    const uint32_t* Kg = g_k + ((size_t)(b * Ls)) * 512 + h * 64;
    const size_t rowbase = (size_t)(h * Bn + b) * Ls + q0;

    const int a_off = ((lane&7) + ((lane>>3)&1)*8)*APADU + (lane>>4)*4;
    const int b_off = (lane&7)*APADU + ((lane>>3)&1)*4 + (lane>>4)*32;
    const uint32_t qs_sh = smem_u32(Qs) + (wm*64*APADU + a_off)*4;
    uint32_t k_sh[2];
    k_sh[0] = smem_u32(Kbuf[0]) + (wn*32*APADU + b_off)*4;
    k_sh[1] = smem_u32(Kbuf[1]) + (wn*32*APADU + b_off)*4;

#pragma unroll
    for (int i = 0; i < 16; i++) {
        int id = tid + i * 128;
        int row = id >> 4, seg = (id & 15) * 4;
        cp_async16(Qs + row*APADU + seg, Qg + (size_t)row * 512 + seg);
    }
    CP_COMMIT();

#define K_LOAD(buf, t_) do {                                                    \
        _Pragma("unroll")                                                       \
        for (int i = 0; i < 8; i++) {                                           \
            int id = tid + i * 128;                                             \
            int row = id >> 4, seg = (id & 15) * 4;                             \
            cp_async16(Kbuf[buf] + row*APADU + seg,                             \
                       Kg + (size_t)((t_)*64 + row) * 512 + seg);               \
        }                                                                       \
    } while (0)

    K_LOAD(0, 0); CP_COMMIT();
    K_LOAD(1, 1); CP_COMMIT();

    float rm[8], rs[8];
    int ridx[8];
#pragma unroll
    for (int i = 0; i < 8; i++) { rm[i] = -1e30f; rs[i] = 0.f; ridx[i] = 0; }

    for (int t = 0; t < 16; t++) {
        if (t < 15) CP_WAIT1(); else CP_WAIT0();
        __syncthreads();
        const int buf = t & 1;

        ACC_INIT()

#pragma unroll
        for (int ks = 0; ks < 4; ks++) {            // dk=64 = 32 pairs = 4 k16-steps
            uint32_t bfr[4][4];
#pragma unroll
            for (int nt = 0; nt < 4; nt++)
                ldsm4(bfr[nt], k_sh[buf] + (nt*8*APADU + ks*8)*4);
#pragma unroll
            for (int mt = 0; mt < 4; mt++) {
                uint32_t ah[4], al[4];
                uint32_t aa = qs_sh + (mt*16*APADU + ks*8)*4;
                ldsm4(ah, aa);
                ldsm4(al, aa + 128);
#pragma unroll
                for (int nt = 0; nt < 4; nt++) {
                    mma16h(acc[mt][nt], ah, bfr[nt]);
                    mma16h(acc[mt][nt], ah, bfr[nt] + 2);
                    mma16h(acc[mt][nt], al, bfr[nt]);
                }
            }
        }

        // streaming zero-fill of this CTA's attn slice, s-range [t*64, t*64+64)
        {
            float4 z4 = make_float4(0.f, 0.f, 0.f, 0.f);
#pragma unroll
            for (int i = 0; i < 16; i++) {
                int id = tid + i * 128;
                int r = id >> 4, f4 = id & 15;
                __stcs((float4*)(attn + (rowbase + r) * Ls + t * 64 + f4 * 4), z4);
            }
        }

        // fold tile into per-thread stats (raw sum via MUFU ex2 + explicit argmax)
        const int sbase = t * 64 + wn * 32 + 2 * lc;
#pragma unroll
        for (int mt = 0; mt < 4; mt++) {
#pragma unroll
            for (int half = 0; half < 2; half++) {
                const int r8 = mt * 2 + half;
                float m = rm[r8], s_ = rs[r8];
                int id_ = ridx[r8];
#pragma unroll
                for (int nt = 0; nt < 4; nt++) {
#pragma unroll
                    for (int j = 0; j < 2; j++) {
                        float v = acc[mt][nt][half*2 + j];
                        if (v > m) { m = v; id_ = sbase + nt*8 + j; }
                        s_ += fex2(v * CCH);
                    }
                }
                rm[r8] = m; rs[r8] = s_; ridx[r8] = id_;
            }
        }
        __syncthreads();
        if (t + 2 < 16) { K_LOAD(buf, t + 2); CP_COMMIT(); }
    }

    // quad reduce over lc
#pragma unroll
    for (int r8 = 0; r8 < 8; r8++) {
        float m = rm[r8], s_ = rs[r8];
        int id_ = ridx[r8];
#pragma unroll
        for (int off = 1; off <= 2; off <<= 1) {
            float om = __shfl_xor_sync(0xffffffffu, m, off);
            float os = __shfl_xor_sync(0xffffffffu, s_, off);
            int   oi = __shfl_xor_sync(0xffffffffu, id_, off);
            s_ += os;
            if (om > m) { m = om; id_ = oi; }
        }
        if (lc == 0) {
            int rowl = wm*64 + (r8 >> 1)*16 + (r8 & 1)*8 + lr;
            redm[rowl*2 + wn] = m;
            reds[rowl*2 + wn] = s_;
            redi[rowl*2 + wn] = id_;
        }
    }
    __syncthreads();

    {
        float m = redm[tid*2], s_ = reds[tid*2];
        int id_ = redi[tid*2];
        float om = redm[tid*2 + 1];
        s_ += reds[tid*2 + 1];
        if (om > m) { m = om; id_ = redi[tid*2 + 1]; }
        float p = fex2(m * CCH) / s_;
        int row = (int)(rowbase) + tid;
        g_p[row] = p;
        g_amax[row] = id_;
        attn[(rowbase + tid) * Ls + id_] = p;
    }
#undef K_LOAD
}

// ============================================================================
// attn @ V gather -> packed bf16 headout pairs
// ============================================================================
__global__ void gather_kernel()
{
    int idx4 = blockIdx.x * blockDim.x + threadIdx.x;
    if (idx4 >= M_ALL * Dm / 4) return;
    int e4 = idx4 & 15;
    int h  = (idx4 >> 4) & 7;
    int m  = idx4 >> 7;
    int b  = m >> 10;
    int q  = m & 1023;
    int row = (h * Bn + b) * Ls + q;
    float p = g_p[row];
    int   s = g_amax[row];
    float4 v = *(const float4*)(g_vs + ((size_t)(b * Ls + s)) * Dm + h * 64 + e4 * 4);
    uint32_t h0, l0, h1, l1;
    split2(v.x * p, v.y * p, h0, l0);
    split2(v.z * p, v.w * p, h1, l1);
    int pairbase = h * 32 + e4 * 2;
    *(uint2*)(g_ho + (size_t)m * 512 + pairbase)       = make_uint2(h0, h1);
    *(uint2*)(g_ho + (size_t)m * 512 + 256 + pairbase) = make_uint2(l0, l1);
}

// ============================================================================
extern "C" void kernel_launch(void* const* d_in, const int* in_sizes, int n_in,
                              void* d_out, int out_size)
{
    const float* q_data = (const float*)d_in[0];
    const float* k_data = (const float*)d_in[1];
    const float* v_data = (const float*)d_in[2];
    const float* w_qs   = (const float*)d_in[3];
    const float* w_ks   = (const float*)d_in[4];
    const float* w_vs   = (const float*)d_in[5];
    const float* proj_w = (const float*)d_in[6];
    const float* proj_b = (const float*)d_in[7];
    const float* lin_w  = (const float*)d_in[8];
    const float* lin_b  = (const float*)d_in[9];

    float* out  = (float*)d_out;                    // [B, L, D]
    float* attn = out + OUT_ELEMS;                  // [H*B, L, L]

    cudaFuncSetAttribute(qkv_pk,  cudaFuncAttributeMaxDynamicSharedMemorySize, PK_SMEM);
    cudaFuncSetAttribute(proj_pk, cudaFuncAttributeMaxDynamicSharedMemorySize, PK_SMEM);
    cudaFuncSetAttribute(lin_pk,  cudaFuncAttributeMaxDynamicSharedMemorySize, PK_SMEM);
    cudaFuncSetAttribute(attn_stats_mma, cudaFuncAttributeMaxDynamicSharedMemorySize, S_SMEM);

    // 0) pre-split all MMA inputs into packed-pair arrays
    prep_act<<<3 * M_ALL * 128 / 256, 256>>>(q_data, k_data, v_data);
    prep_w<<<(3*8*256*64 + 512*128 + 512*256 + 255) / 256, 256>>>(w_qs, w_ks, w_vs,
                                                                  proj_w, lin_w);

    // 1) Q/K/V projections (pure ldmatrix+HMMA; Q,K fp16x3, V bf16x3)
    qkv_pk<<<dim3(8, 128, 3), 128, PK_SMEM>>>();

    // 2) QK^T + softmax stats + dense attn fill (pure ldmatrix+HMMA)
    attn_stats_mma<<<dim3(8, 16, 8), 128, S_SMEM>>>(attn);

    // 3) attn @ V gather -> packed bf16 headout
    gather_kernel<<<(M_ALL * Dm / 4 + 255) / 256, 256>>>();

    // 4) output projection -> packed bf16 projout
    proj_pk<<<dim3(8, 128), 128, PK_SMEM>>>(proj_b);

    // 5) final linear: out = [q_data | projout] @ lin_w^T + lin_b
    lin_pk<<<dim3(8, 128), 128, PK_SMEM>>>(lin_b, out);
}